// round 1
// baseline (speedup 1.0000x reference)
#include <cuda_runtime.h>

#define EMB 1024
#define BATCH 2
#define SLEN 2048
#define HEADS 16
#define DHEAD 64
#define MTOT (BATCH * SLEN)   // 4096

// Scratch (allocation-free rule: __device__ globals)
__device__ float g_q[MTOT * EMB];
__device__ float g_k[MTOT * EMB];
__device__ float g_v[MTOT * EMB];
__device__ float g_attn[MTOT * EMB];

// ---------------------------------------------------------------------------
// GEMM: Y[M,N] = X[M,K] * W[K,N] + bias[N]
// 128x128 block tile, BK=16, 256 threads, 8x8 per thread. M,N,K multiples of 128/16.
// ---------------------------------------------------------------------------
__global__ __launch_bounds__(256, 2)
void gemm_bias(const float* __restrict__ X, const float* __restrict__ W,
               const float* __restrict__ bias, float* __restrict__ Y,
               int M, int N, int K) {
    __shared__ float As[16][132];   // transposed A tile: As[k][m]
    __shared__ float Bs[16][132];   // Bs[k][n]

    const int tid = threadIdx.x;
    const int tx = tid & 15;
    const int ty = tid >> 4;
    const int m0 = blockIdx.y * 128;
    const int n0 = blockIdx.x * 128;

    float acc[8][8];
#pragma unroll
    for (int i = 0; i < 8; i++)
#pragma unroll
        for (int j = 0; j < 8; j++) acc[i][j] = 0.f;

    for (int k0 = 0; k0 < K; k0 += 16) {
#pragma unroll
        for (int half = 0; half < 2; half++) {
            int f = tid + half * 256;
            // A tile load (float4 along K), scatter transposed
            int row = f >> 2;             // 0..127
            int kg  = (f & 3) << 2;       // 0,4,8,12
            float4 a = *(const float4*)&X[(size_t)(m0 + row) * K + k0 + kg];
            As[kg + 0][row] = a.x;
            As[kg + 1][row] = a.y;
            As[kg + 2][row] = a.z;
            As[kg + 3][row] = a.w;
            // B tile load (direct)
            int kr = f >> 5;              // 0..15
            int nc = (f & 31) << 2;       // 0..124
            *(float4*)&Bs[kr][nc] = *(const float4*)&W[(size_t)(k0 + kr) * N + n0 + nc];
        }
        __syncthreads();

#pragma unroll
        for (int kk = 0; kk < 16; kk++) {
            float a[8], b[8];
            *(float4*)&a[0] = *(const float4*)&As[kk][ty * 8];
            *(float4*)&a[4] = *(const float4*)&As[kk][ty * 8 + 4];
            *(float4*)&b[0] = *(const float4*)&Bs[kk][tx * 8];
            *(float4*)&b[4] = *(const float4*)&Bs[kk][tx * 8 + 4];
#pragma unroll
            for (int i = 0; i < 8; i++)
#pragma unroll
                for (int j = 0; j < 8; j++)
                    acc[i][j] += a[i] * b[j];
        }
        __syncthreads();
    }

#pragma unroll
    for (int i = 0; i < 8; i++) {
        int row = m0 + ty * 8 + i;
#pragma unroll
        for (int j = 0; j < 8; j += 4) {
            int col = n0 + tx * 8 + j;
            float4 o;
            o.x = acc[i][j + 0] + bias[col + 0];
            o.y = acc[i][j + 1] + bias[col + 1];
            o.z = acc[i][j + 2] + bias[col + 2];
            o.w = acc[i][j + 3] + bias[col + 3];
            *(float4*)&Y[(size_t)row * N + col] = o;
        }
    }
}

// ---------------------------------------------------------------------------
// Flash attention (no mask): per block = 128 queries x one (b,h).
// Br=128, Bc=64, D=64. 256 threads (16x16): each thread owns 8 S/O rows,
// 4 S cols (= 4 O dims). Online softmax; shfl reductions over 16-lane group.
// ---------------------------------------------------------------------------
#define BR 128
#define BC 64
// smem floats: QsT 64*128, KsT 64*68, Vs 64*64, Ps 128*64
#define Q_OFF   0
#define K_OFF   (64 * 128)
#define V_OFF   (K_OFF + 64 * 68)
#define P_OFF   (V_OFF + 64 * 64)
#define ATTN_SMEM_FLOATS (P_OFF + 128 * 64)
#define ATTN_SMEM_BYTES  (ATTN_SMEM_FLOATS * 4)

__global__ __launch_bounds__(256, 2)
void flash_attn(const float* __restrict__ gq, const float* __restrict__ gk,
                const float* __restrict__ gv, float* __restrict__ gout) {
    extern __shared__ float sm[];
    float* QsT = sm + Q_OFF;   // [k][r] stride 128
    float* KsT = sm + K_OFF;   // [k][c] stride 68
    float* Vs  = sm + V_OFF;   // [c][d] stride 64
    float* Ps  = sm + P_OFF;   // [r][c] stride 64

    const int tid = threadIdx.x;
    const int tx = tid & 15;
    const int ty = tid >> 4;
    const int qt = blockIdx.x;                  // 0..15
    const int bh = blockIdx.y;                  // 0..31
    const int b  = bh / HEADS;
    const int h  = bh % HEADS;
    const int qbase = qt * BR;
    const size_t rowbase = (size_t)b * SLEN;
    const float scale = 0.125f;                 // 1/sqrt(64)

    // Load Q tile transposed (and pre-scaled): QsT[k][r] = Q[qbase+r][h*64+k]*scale
    for (int f = tid; f < BR * (DHEAD / 4); f += 256) {
        int r  = f >> 4;                        // 0..127
        int kg = (f & 15) << 2;                 // 0..60
        float4 qv = *(const float4*)&gq[(rowbase + qbase + r) * EMB + h * DHEAD + kg];
        QsT[(kg + 0) * 128 + r] = qv.x * scale;
        QsT[(kg + 1) * 128 + r] = qv.y * scale;
        QsT[(kg + 2) * 128 + r] = qv.z * scale;
        QsT[(kg + 3) * 128 + r] = qv.w * scale;
    }

    float m[8], l[8], acc[8][4];
#pragma unroll
    for (int i = 0; i < 8; i++) {
        m[i] = -1e30f;
        l[i] = 0.f;
#pragma unroll
        for (int j = 0; j < 4; j++) acc[i][j] = 0.f;
    }

    const int r0 = ty * 8;   // owned S/O rows
    const int c0 = tx * 4;   // owned S cols / O dims

    for (int kt = 0; kt < SLEN; kt += BC) {
        __syncthreads();   // previous iteration done with KsT/Vs/Ps
        // Load K tile transposed + V tile
        for (int f = tid; f < BC * (DHEAD / 4); f += 256) {
            int c  = f >> 4;                    // 0..63
            int kg = (f & 15) << 2;
            const size_t gidx = (rowbase + kt + c) * EMB + h * DHEAD + kg;
            float4 kv = *(const float4*)&gk[gidx];
            KsT[(kg + 0) * 68 + c] = kv.x;
            KsT[(kg + 1) * 68 + c] = kv.y;
            KsT[(kg + 2) * 68 + c] = kv.z;
            KsT[(kg + 3) * 68 + c] = kv.w;
            *(float4*)&Vs[c * 64 + kg] = *(const float4*)&gv[gidx];
        }
        __syncthreads();

        // S = (Q*scale) K^T
        float s[8][4];
#pragma unroll
        for (int i = 0; i < 8; i++)
#pragma unroll
            for (int j = 0; j < 4; j++) s[i][j] = 0.f;

#pragma unroll 4
        for (int k = 0; k < DHEAD; k++) {
            float a[8], kb[4];
            *(float4*)&a[0]  = *(const float4*)&QsT[k * 128 + r0];
            *(float4*)&a[4]  = *(const float4*)&QsT[k * 128 + r0 + 4];
            *(float4*)&kb[0] = *(const float4*)&KsT[k * 68 + c0];
#pragma unroll
            for (int i = 0; i < 8; i++)
#pragma unroll
                for (int j = 0; j < 4; j++)
                    s[i][j] += a[i] * kb[j];
        }

        // Online softmax update per row; write P tile
#pragma unroll
        for (int i = 0; i < 8; i++) {
            float mx = fmaxf(fmaxf(s[i][0], s[i][1]), fmaxf(s[i][2], s[i][3]));
#pragma unroll
            for (int off = 1; off < 16; off <<= 1)
                mx = fmaxf(mx, __shfl_xor_sync(0xffffffffu, mx, off));
            float mnew = fmaxf(m[i], mx);
            float corr = __expf(m[i] - mnew);
            m[i] = mnew;
            float rs = 0.f;
#pragma unroll
            for (int j = 0; j < 4; j++) {
                float p = __expf(s[i][j] - mnew);
                s[i][j] = p;
                rs += p;
            }
#pragma unroll
            for (int off = 1; off < 16; off <<= 1)
                rs += __shfl_xor_sync(0xffffffffu, rs, off);
            l[i] = l[i] * corr + rs;
#pragma unroll
            for (int j = 0; j < 4; j++) acc[i][j] *= corr;
            *(float4*)&Ps[(r0 + i) * 64 + c0] = *(float4*)&s[i][0];
        }
        __syncthreads();

        // O += P * V   (O cols = c0..c0+3 of D)
#pragma unroll 2
        for (int c4 = 0; c4 < BC; c4 += 4) {
            float v4[4][4];
#pragma unroll
            for (int cc = 0; cc < 4; cc++)
                *(float4*)&v4[cc][0] = *(const float4*)&Vs[(c4 + cc) * 64 + c0];
#pragma unroll
            for (int i = 0; i < 8; i++) {
                float p4[4];
                *(float4*)&p4[0] = *(const float4*)&Ps[(r0 + i) * 64 + c4];
#pragma unroll
                for (int cc = 0; cc < 4; cc++)
#pragma unroll
                    for (int j = 0; j < 4; j++)
                        acc[i][j] += p4[cc] * v4[cc][j];
            }
        }
    }

    // Normalize and write: out[b, qbase+r, h*64 + d]
#pragma unroll
    for (int i = 0; i < 8; i++) {
        float inv = 1.f / l[i];
        float4 o;
        o.x = acc[i][0] * inv;
        o.y = acc[i][1] * inv;
        o.z = acc[i][2] * inv;
        o.w = acc[i][3] * inv;
        *(float4*)&gout[(rowbase + qbase + r0 + i) * EMB + h * DHEAD + c0] = o;
    }
}

// ---------------------------------------------------------------------------
extern "C" void kernel_launch(void* const* d_in, const int* in_sizes, int n_in,
                              void* d_out, int out_size) {
    const float* query = (const float*)d_in[0];
    const float* key   = (const float*)d_in[1];
    const float* value = (const float*)d_in[2];
    const float* Wq    = (const float*)d_in[3];
    const float* Wk    = (const float*)d_in[4];
    const float* Wv    = (const float*)d_in[5];
    const float* Wo    = (const float*)d_in[6];
    const float* Bq    = (const float*)d_in[7];
    const float* Bk    = (const float*)d_in[8];
    const float* Bv    = (const float*)d_in[9];
    const float* Bo    = (const float*)d_in[10];

    float *q, *k, *v, *attn;
    cudaGetSymbolAddress((void**)&q,    g_q);
    cudaGetSymbolAddress((void**)&k,    g_k);
    cudaGetSymbolAddress((void**)&v,    g_v);
    cudaGetSymbolAddress((void**)&attn, g_attn);

    dim3 gblk(256);
    dim3 ggrid(EMB / 128, MTOT / 128);   // (8, 32)

    gemm_bias<<<ggrid, gblk>>>(query, Wq, Bq, q, MTOT, EMB, EMB);
    gemm_bias<<<ggrid, gblk>>>(key,   Wk, Bk, k, MTOT, EMB, EMB);
    gemm_bias<<<ggrid, gblk>>>(value, Wv, Bv, v, MTOT, EMB, EMB);

    cudaFuncSetAttribute(flash_attn, cudaFuncAttributeMaxDynamicSharedMemorySize,
                         ATTN_SMEM_BYTES);
    flash_attn<<<dim3(SLEN / BR, BATCH * HEADS), 256, ATTN_SMEM_BYTES>>>(q, k, v, attn);

    gemm_bias<<<ggrid, gblk>>>(attn, Wo, Bo, (float*)d_out, MTOT, EMB, EMB);
}

// round 2
// speedup vs baseline: 2.6547x; 2.6547x over previous
#include <cuda_runtime.h>
#include <cstdint>

#define EMB 1024
#define BATCH 2
#define SLEN 2048
#define HEADS 16
#define DHEAD 64
#define MTOT (BATCH * SLEN)   // 4096

__device__ float g_q[MTOT * EMB];
__device__ float g_k[MTOT * EMB];
__device__ float g_v[MTOT * EMB];
__device__ float g_attn[MTOT * EMB];

// ---------------------------------------------------------------------------
// tf32 mma helpers (m16n8k8, row.col, f32 accumulate)
// Fragment layout (g = lane>>2, t = lane&3):
//   A: a0=(g,t) a1=(g+8,t) a2=(g,t+4) a3=(g+8,t+4)
//   B: b0=(t,g) b1=(t+4,g)           (row = k, col = n)
//   C: c0=(g,2t) c1=(g,2t+1) c2=(g+8,2t) c3=(g+8,2t+1)
// ---------------------------------------------------------------------------
__device__ __forceinline__ uint32_t f2tf(float f) {
    uint32_t u; asm("cvt.rna.tf32.f32 %0, %1;" : "=r"(u) : "f"(f)); return u;
}
__device__ __forceinline__ uint32_t smaddr(const void* p) {
    return (uint32_t)__cvta_generic_to_shared(p);
}
__device__ __forceinline__ void ldm4(uint32_t a[4], uint32_t addr) {
    asm volatile("ldmatrix.sync.aligned.m8n8.x4.shared.b16 {%0,%1,%2,%3}, [%4];"
                 : "=r"(a[0]), "=r"(a[1]), "=r"(a[2]), "=r"(a[3]) : "r"(addr));
}
__device__ __forceinline__ void mma8(float c[4], const uint32_t a[4],
                                     uint32_t b0, uint32_t b1) {
    asm volatile(
        "mma.sync.aligned.m16n8k8.row.col.f32.tf32.tf32.f32 "
        "{%0,%1,%2,%3}, {%4,%5,%6,%7}, {%8,%9}, {%0,%1,%2,%3};"
        : "+f"(c[0]), "+f"(c[1]), "+f"(c[2]), "+f"(c[3])
        : "r"(a[0]), "r"(a[1]), "r"(a[2]), "r"(a[3]), "r"(b0), "r"(b1));
}

// ---------------------------------------------------------------------------
// GEMM: Y[M,N] = X[M,K]*W[K,N] + bias.  128x128 tile, BK=32, 256 thr, tf32 mma.
// As[row][k] stride 36 (ldmatrix A side). Bs[k][n] stride 136 (scalar B frags,
// bank = 8t+g -> conflict-free). Register-prefetch double buffer.
// ---------------------------------------------------------------------------
#define ASTR 36
#define BSTR 136
#define A_WORDS (128 * ASTR)
#define B_WORDS (32 * BSTR)
#define GEMM_SMEM ((2 * A_WORDS + 2 * B_WORDS) * 4)

__global__ __launch_bounds__(256, 1)
void gemm_tf32(const float* __restrict__ X, const float* __restrict__ W,
               const float* __restrict__ bias, float* __restrict__ Y,
               int M, int N, int K) {
    extern __shared__ uint32_t sh[];
    uint32_t* AsBase = sh;
    uint32_t* BsBase = sh + 2 * A_WORDS;

    const int tid = threadIdx.x;
    const int lane = tid & 31;
    const int g = lane >> 2, t = lane & 3;
    const int wid = tid >> 5;
    const int wm = (wid >> 2) * 64;
    const int wn = (wid & 3) * 32;
    const int m0 = blockIdx.y * 128;
    const int n0 = blockIdx.x * 128;

    const float* Aptr = X + (size_t)m0 * K;
    const float* Bptr = W + n0;

    float acc[4][4][4];
#pragma unroll
    for (int i = 0; i < 4; i++)
#pragma unroll
        for (int j = 0; j < 4; j++)
#pragma unroll
            for (int q = 0; q < 4; q++) acc[i][j][q] = 0.f;

    float4 pa[4], pb[4];
    // prefetch tile 0
#pragma unroll
    for (int it = 0; it < 4; it++) {
        int f = tid + it * 256;
        pa[it] = *(const float4*)&Aptr[(size_t)(f >> 3) * K + (f & 7) * 4];
        pb[it] = *(const float4*)&Bptr[(size_t)(f >> 5) * N + (f & 31) * 4];
    }
    // store tile 0
#pragma unroll
    for (int it = 0; it < 4; it++) {
        int f = tid + it * 256;
        *(uint4*)&AsBase[(f >> 3) * ASTR + (f & 7) * 4] =
            make_uint4(f2tf(pa[it].x), f2tf(pa[it].y), f2tf(pa[it].z), f2tf(pa[it].w));
        *(uint4*)&BsBase[(f >> 5) * BSTR + (f & 31) * 4] =
            make_uint4(f2tf(pb[it].x), f2tf(pb[it].y), f2tf(pb[it].z), f2tf(pb[it].w));
    }
    __syncthreads();

    const int nit = K / 32;
    for (int itk = 0; itk < nit; itk++) {
        if (itk + 1 < nit) {
            int k0n = (itk + 1) * 32;
#pragma unroll
            for (int it = 0; it < 4; it++) {
                int f = tid + it * 256;
                pa[it] = *(const float4*)&Aptr[(size_t)(f >> 3) * K + k0n + (f & 7) * 4];
                pb[it] = *(const float4*)&Bptr[(size_t)(k0n + (f >> 5)) * N + (f & 31) * 4];
            }
        }
        const uint32_t* as = AsBase + (itk & 1) * A_WORDS;
        const uint32_t* bs = BsBase + (itk & 1) * B_WORDS;
#pragma unroll
        for (int ks = 0; ks < 4; ks++) {
            const int k0 = ks * 8;
            uint32_t a[4][4];
#pragma unroll
            for (int mi = 0; mi < 4; mi++)
                ldm4(a[mi], smaddr(&as[(wm + 16 * mi + (lane & 15)) * ASTR +
                                       k0 + (lane >> 4) * 4]));
            uint32_t b[4][2];
#pragma unroll
            for (int nj = 0; nj < 4; nj++) {
                b[nj][0] = bs[(k0 + t) * BSTR + wn + 8 * nj + g];
                b[nj][1] = bs[(k0 + t + 4) * BSTR + wn + 8 * nj + g];
            }
#pragma unroll
            for (int mi = 0; mi < 4; mi++)
#pragma unroll
                for (int nj = 0; nj < 4; nj++)
                    mma8(acc[mi][nj], a[mi], b[nj][0], b[nj][1]);
        }
        if (itk + 1 < nit) {
            uint32_t* asw = AsBase + ((itk + 1) & 1) * A_WORDS;
            uint32_t* bsw = BsBase + ((itk + 1) & 1) * B_WORDS;
#pragma unroll
            for (int it = 0; it < 4; it++) {
                int f = tid + it * 256;
                *(uint4*)&asw[(f >> 3) * ASTR + (f & 7) * 4] =
                    make_uint4(f2tf(pa[it].x), f2tf(pa[it].y), f2tf(pa[it].z), f2tf(pa[it].w));
                *(uint4*)&bsw[(f >> 5) * BSTR + (f & 31) * 4] =
                    make_uint4(f2tf(pb[it].x), f2tf(pb[it].y), f2tf(pb[it].z), f2tf(pb[it].w));
            }
            __syncthreads();
        }
    }

    // epilogue
#pragma unroll
    for (int mi = 0; mi < 4; mi++) {
#pragma unroll
        for (int nj = 0; nj < 4; nj++) {
            int col = n0 + wn + 8 * nj + 2 * t;
            float b0v = bias[col], b1v = bias[col + 1];
            int row = m0 + wm + 16 * mi + g;
            float2 o0 = make_float2(acc[mi][nj][0] + b0v, acc[mi][nj][1] + b1v);
            *(float2*)&Y[(size_t)row * N + col] = o0;
            float2 o1 = make_float2(acc[mi][nj][2] + b0v, acc[mi][nj][3] + b1v);
            *(float2*)&Y[(size_t)(row + 8) * N + col] = o1;
        }
    }
}

// ---------------------------------------------------------------------------
// Flash attention, tf32 mma. Block = 128 queries x one (b,h); 8 warps, each
// owns 16 query rows. Bc=64 keys/iter. K and V read straight from natural
// [key][d] smem layout (K via ldmatrix as col-major B; V via scalar B frags,
// bank 4t+g conflict-free). P staged in smem (warp-private -> __syncwarp).
// ---------------------------------------------------------------------------
#define FSTR 68
#define FQ_OFF 0
#define FK_OFF (128 * FSTR)
#define FV_OFF (FK_OFF + 64 * FSTR)
#define FP_OFF (FV_OFF + 64 * FSTR)
#define ATTN_SMEM ((FP_OFF + 128 * FSTR) * 4)

__global__ __launch_bounds__(256, 2)
void flash_mma(const float* __restrict__ gq, const float* __restrict__ gk,
               const float* __restrict__ gv, float* __restrict__ go) {
    extern __shared__ uint32_t sh[];
    uint32_t* Qs = sh + FQ_OFF;
    uint32_t* Ks = sh + FK_OFF;
    uint32_t* Vs = sh + FV_OFF;
    uint32_t* Ps = sh + FP_OFF;

    const int tid = threadIdx.x;
    const int lane = tid & 31;
    const int g = lane >> 2, t = lane & 3;
    const int wid = tid >> 5;
    const int r0 = wid * 16;
    const int qt = blockIdx.x;
    const int bh = blockIdx.y;
    const int b = bh >> 4, h = bh & 15;
    const int qbase = qt * 128;
    const size_t rowbase = (size_t)b * SLEN;
    const float scale = 0.125f;

    // Load Q tile (pre-scaled, tf32)
#pragma unroll
    for (int it = 0; it < 8; it++) {
        int f = tid + it * 256;
        int row = f >> 4, c4 = (f & 15) * 4;
        float4 qv = *(const float4*)&gq[(rowbase + qbase + row) * EMB + h * DHEAD + c4];
        *(uint4*)&Qs[row * FSTR + c4] =
            make_uint4(f2tf(qv.x * scale), f2tf(qv.y * scale),
                       f2tf(qv.z * scale), f2tf(qv.w * scale));
    }

    float o[8][4];
#pragma unroll
    for (int j = 0; j < 8; j++)
#pragma unroll
        for (int q = 0; q < 4; q++) o[j][q] = 0.f;
    float m0v = -1e30f, m1v = -1e30f, l0 = 0.f, l1 = 0.f;

    for (int kt = 0; kt < SLEN; kt += 64) {
        __syncthreads();   // Ks/Vs free (and Q visible on first iter)
#pragma unroll
        for (int it = 0; it < 4; it++) {
            int f = tid + it * 256;
            int row = f >> 4, c4 = (f & 15) * 4;
            size_t gidx = (rowbase + kt + row) * EMB + h * DHEAD + c4;
            float4 kv = *(const float4*)&gk[gidx];
            *(uint4*)&Ks[row * FSTR + c4] =
                make_uint4(f2tf(kv.x), f2tf(kv.y), f2tf(kv.z), f2tf(kv.w));
            float4 vv = *(const float4*)&gv[gidx];
            *(uint4*)&Vs[row * FSTR + c4] =
                make_uint4(f2tf(vv.x), f2tf(vv.y), f2tf(vv.z), f2tf(vv.w));
        }
        __syncthreads();

        // S = Q K^T  (16 x 64 per warp)
        float s[8][4];
#pragma unroll
        for (int j = 0; j < 8; j++)
#pragma unroll
            for (int q = 0; q < 4; q++) s[j][q] = 0.f;

#pragma unroll
        for (int ks = 0; ks < 8; ks++) {
            const int k0 = ks * 8;
            uint32_t aq[4];
            ldm4(aq, smaddr(&Qs[(r0 + (lane & 15)) * FSTR + k0 + (lane >> 4) * 4]));
            const int brow = (lane & 7) + ((lane >> 4) << 3);
            const int bchk = ((lane >> 3) & 1) * 4;
#pragma unroll
            for (int jj = 0; jj < 4; jj++) {
                uint32_t bb[4];
                ldm4(bb, smaddr(&Ks[(jj * 16 + brow) * FSTR + k0 + bchk]));
                mma8(s[2 * jj], aq, bb[0], bb[1]);
                mma8(s[2 * jj + 1], aq, bb[2], bb[3]);
            }
        }

        // online softmax (rows g and g+8 of this warp's 16)
        float rmax0 = -1e30f, rmax1 = -1e30f;
#pragma unroll
        for (int j = 0; j < 8; j++) {
            rmax0 = fmaxf(rmax0, fmaxf(s[j][0], s[j][1]));
            rmax1 = fmaxf(rmax1, fmaxf(s[j][2], s[j][3]));
        }
        rmax0 = fmaxf(rmax0, __shfl_xor_sync(0xffffffffu, rmax0, 1));
        rmax0 = fmaxf(rmax0, __shfl_xor_sync(0xffffffffu, rmax0, 2));
        rmax1 = fmaxf(rmax1, __shfl_xor_sync(0xffffffffu, rmax1, 1));
        rmax1 = fmaxf(rmax1, __shfl_xor_sync(0xffffffffu, rmax1, 2));
        float mn0 = fmaxf(m0v, rmax0), mn1 = fmaxf(m1v, rmax1);
        float cor0 = __expf(m0v - mn0), cor1 = __expf(m1v - mn1);
        m0v = mn0; m1v = mn1;
        float sum0 = 0.f, sum1 = 0.f;
#pragma unroll
        for (int j = 0; j < 8; j++) {
            s[j][0] = __expf(s[j][0] - mn0);
            s[j][1] = __expf(s[j][1] - mn0);
            s[j][2] = __expf(s[j][2] - mn1);
            s[j][3] = __expf(s[j][3] - mn1);
            sum0 += s[j][0] + s[j][1];
            sum1 += s[j][2] + s[j][3];
        }
        sum0 += __shfl_xor_sync(0xffffffffu, sum0, 1);
        sum0 += __shfl_xor_sync(0xffffffffu, sum0, 2);
        sum1 += __shfl_xor_sync(0xffffffffu, sum1, 1);
        sum1 += __shfl_xor_sync(0xffffffffu, sum1, 2);
        l0 = l0 * cor0 + sum0;
        l1 = l1 * cor1 + sum1;
#pragma unroll
        for (int j = 0; j < 8; j++) {
            o[j][0] *= cor0; o[j][1] *= cor0;
            o[j][2] *= cor1; o[j][3] *= cor1;
            *(uint2*)&Ps[(r0 + g) * FSTR + 8 * j + 2 * t] =
                make_uint2(f2tf(s[j][0]), f2tf(s[j][1]));
            *(uint2*)&Ps[(r0 + 8 + g) * FSTR + 8 * j + 2 * t] =
                make_uint2(f2tf(s[j][2]), f2tf(s[j][3]));
        }
        __syncwarp();

        // O += P V   (16 x 64 per warp)
#pragma unroll
        for (int ks = 0; ks < 8; ks++) {
            const int k0 = ks * 8;
            uint32_t ap[4];
            ldm4(ap, smaddr(&Ps[(r0 + (lane & 15)) * FSTR + k0 + (lane >> 4) * 4]));
#pragma unroll
            for (int j = 0; j < 8; j++) {
                uint32_t v0 = Vs[(k0 + t) * FSTR + 8 * j + g];
                uint32_t v1 = Vs[(k0 + t + 4) * FSTR + 8 * j + g];
                mma8(o[j], ap, v0, v1);
            }
        }
        __syncwarp();   // Ps reads done before next iteration's writes
    }

    const float inv0 = 1.f / l0, inv1 = 1.f / l1;
#pragma unroll
    for (int j = 0; j < 8; j++) {
        int col = h * DHEAD + 8 * j + 2 * t;
        size_t row = rowbase + qbase + r0 + g;
        *(float2*)&go[row * EMB + col] = make_float2(o[j][0] * inv0, o[j][1] * inv0);
        *(float2*)&go[(row + 8) * EMB + col] = make_float2(o[j][2] * inv1, o[j][3] * inv1);
    }
}

// ---------------------------------------------------------------------------
extern "C" void kernel_launch(void* const* d_in, const int* in_sizes, int n_in,
                              void* d_out, int out_size) {
    const float* query = (const float*)d_in[0];
    const float* key   = (const float*)d_in[1];
    const float* value = (const float*)d_in[2];
    const float* Wq    = (const float*)d_in[3];
    const float* Wk    = (const float*)d_in[4];
    const float* Wv    = (const float*)d_in[5];
    const float* Wo    = (const float*)d_in[6];
    const float* Bq    = (const float*)d_in[7];
    const float* Bk    = (const float*)d_in[8];
    const float* Bv    = (const float*)d_in[9];
    const float* Bo    = (const float*)d_in[10];

    float *q, *k, *v, *attn;
    cudaGetSymbolAddress((void**)&q,    g_q);
    cudaGetSymbolAddress((void**)&k,    g_k);
    cudaGetSymbolAddress((void**)&v,    g_v);
    cudaGetSymbolAddress((void**)&attn, g_attn);

    cudaFuncSetAttribute(gemm_tf32, cudaFuncAttributeMaxDynamicSharedMemorySize, GEMM_SMEM);
    cudaFuncSetAttribute(flash_mma, cudaFuncAttributeMaxDynamicSharedMemorySize, ATTN_SMEM);

    dim3 gblk(256);
    dim3 ggrid(EMB / 128, MTOT / 128);   // (8, 32)

    gemm_tf32<<<ggrid, gblk, GEMM_SMEM>>>(query, Wq, Bq, q, MTOT, EMB, EMB);
    gemm_tf32<<<ggrid, gblk, GEMM_SMEM>>>(key,   Wk, Bk, k, MTOT, EMB, EMB);
    gemm_tf32<<<ggrid, gblk, GEMM_SMEM>>>(value, Wv, Bv, v, MTOT, EMB, EMB);

    flash_mma<<<dim3(SLEN / 128, BATCH * HEADS), gblk, ATTN_SMEM>>>(q, k, v, attn);

    gemm_tf32<<<ggrid, gblk, GEMM_SMEM>>>(attn, Wo, Bo, (float*)d_out, MTOT, EMB, EMB);
}

// round 3
// speedup vs baseline: 3.0683x; 1.1558x over previous
#include <cuda_runtime.h>
#include <cstdint>

#define EMB 1024
#define BATCH 2
#define SLEN 2048
#define HEADS 16
#define DHEAD 64
#define MTOT (BATCH * SLEN)   // 4096

__device__ float g_q[MTOT * EMB];
__device__ float g_k[MTOT * EMB];
__device__ float g_v[MTOT * EMB];
__device__ float g_attn[MTOT * EMB];

// ---------------------------------------------------------------------------
// tf32 mma helpers (m16n8k8, row.col, f32 accumulate)
//   A: a0=(g,t) a1=(g+8,t) a2=(g,t+4) a3=(g+8,t+4)   (g=lane>>2, t=lane&3)
//   B: b0=(t,g) b1=(t+4,g)
//   C: c0=(g,2t) c1=(g,2t+1) c2=(g+8,2t) c3=(g+8,2t+1)
// ---------------------------------------------------------------------------
__device__ __forceinline__ uint32_t f2tf(float f) {
    uint32_t u; asm("cvt.rna.tf32.f32 %0, %1;" : "=r"(u) : "f"(f)); return u;
}
__device__ __forceinline__ uint32_t smaddr(const void* p) {
    return (uint32_t)__cvta_generic_to_shared(p);
}
__device__ __forceinline__ void ldm4(uint32_t a[4], uint32_t addr) {
    asm volatile("ldmatrix.sync.aligned.m8n8.x4.shared.b16 {%0,%1,%2,%3}, [%4];"
                 : "=r"(a[0]), "=r"(a[1]), "=r"(a[2]), "=r"(a[3]) : "r"(addr));
}
__device__ __forceinline__ void mma8(float c[4], const uint32_t a[4],
                                     uint32_t b0, uint32_t b1) {
    asm volatile(
        "mma.sync.aligned.m16n8k8.row.col.f32.tf32.tf32.f32 "
        "{%0,%1,%2,%3}, {%4,%5,%6,%7}, {%8,%9}, {%0,%1,%2,%3};"
        : "+f"(c[0]), "+f"(c[1]), "+f"(c[2]), "+f"(c[3])
        : "r"(a[0]), "r"(a[1]), "r"(a[2]), "r"(a[3]), "r"(b0), "r"(b1));
}
__device__ __forceinline__ void cpasync16(uint32_t saddr, const void* gaddr) {
    asm volatile("cp.async.cg.shared.global [%0], [%1], 16;" :: "r"(saddr), "l"(gaddr));
}

// ---------------------------------------------------------------------------
// GEMM: Y[M,N] = X[M,K]*W[K,N] + bias.  (unchanged from R2)
// ---------------------------------------------------------------------------
#define ASTR 36
#define BSTR 136
#define A_WORDS (128 * ASTR)
#define B_WORDS (32 * BSTR)
#define GEMM_SMEM ((2 * A_WORDS + 2 * B_WORDS) * 4)

__global__ __launch_bounds__(256, 1)
void gemm_tf32(const float* __restrict__ X, const float* __restrict__ W,
               const float* __restrict__ bias, float* __restrict__ Y,
               int M, int N, int K) {
    extern __shared__ uint32_t sh[];
    uint32_t* AsBase = sh;
    uint32_t* BsBase = sh + 2 * A_WORDS;

    const int tid = threadIdx.x;
    const int lane = tid & 31;
    const int g = lane >> 2, t = lane & 3;
    const int wid = tid >> 5;
    const int wm = (wid >> 2) * 64;
    const int wn = (wid & 3) * 32;
    const int m0 = blockIdx.y * 128;
    const int n0 = blockIdx.x * 128;

    const float* Aptr = X + (size_t)m0 * K;
    const float* Bptr = W + n0;

    float acc[4][4][4];
#pragma unroll
    for (int i = 0; i < 4; i++)
#pragma unroll
        for (int j = 0; j < 4; j++)
#pragma unroll
            for (int q = 0; q < 4; q++) acc[i][j][q] = 0.f;

    float4 pa[4], pb[4];
#pragma unroll
    for (int it = 0; it < 4; it++) {
        int f = tid + it * 256;
        pa[it] = *(const float4*)&Aptr[(size_t)(f >> 3) * K + (f & 7) * 4];
        pb[it] = *(const float4*)&Bptr[(size_t)(f >> 5) * N + (f & 31) * 4];
    }
#pragma unroll
    for (int it = 0; it < 4; it++) {
        int f = tid + it * 256;
        *(uint4*)&AsBase[(f >> 3) * ASTR + (f & 7) * 4] =
            make_uint4(f2tf(pa[it].x), f2tf(pa[it].y), f2tf(pa[it].z), f2tf(pa[it].w));
        *(uint4*)&BsBase[(f >> 5) * BSTR + (f & 31) * 4] =
            make_uint4(f2tf(pb[it].x), f2tf(pb[it].y), f2tf(pb[it].z), f2tf(pb[it].w));
    }
    __syncthreads();

    const int nit = K / 32;
    for (int itk = 0; itk < nit; itk++) {
        if (itk + 1 < nit) {
            int k0n = (itk + 1) * 32;
#pragma unroll
            for (int it = 0; it < 4; it++) {
                int f = tid + it * 256;
                pa[it] = *(const float4*)&Aptr[(size_t)(f >> 3) * K + k0n + (f & 7) * 4];
                pb[it] = *(const float4*)&Bptr[(size_t)(k0n + (f >> 5)) * N + (f & 31) * 4];
            }
        }
        const uint32_t* as = AsBase + (itk & 1) * A_WORDS;
        const uint32_t* bs = BsBase + (itk & 1) * B_WORDS;
#pragma unroll
        for (int ks = 0; ks < 4; ks++) {
            const int k0 = ks * 8;
            uint32_t a[4][4];
#pragma unroll
            for (int mi = 0; mi < 4; mi++)
                ldm4(a[mi], smaddr(&as[(wm + 16 * mi + (lane & 15)) * ASTR +
                                       k0 + (lane >> 4) * 4]));
            uint32_t b[4][2];
#pragma unroll
            for (int nj = 0; nj < 4; nj++) {
                b[nj][0] = bs[(k0 + t) * BSTR + wn + 8 * nj + g];
                b[nj][1] = bs[(k0 + t + 4) * BSTR + wn + 8 * nj + g];
            }
#pragma unroll
            for (int mi = 0; mi < 4; mi++)
#pragma unroll
                for (int nj = 0; nj < 4; nj++)
                    mma8(acc[mi][nj], a[mi], b[nj][0], b[nj][1]);
        }
        if (itk + 1 < nit) {
            uint32_t* asw = AsBase + ((itk + 1) & 1) * A_WORDS;
            uint32_t* bsw = BsBase + ((itk + 1) & 1) * B_WORDS;
#pragma unroll
            for (int it = 0; it < 4; it++) {
                int f = tid + it * 256;
                *(uint4*)&asw[(f >> 3) * ASTR + (f & 7) * 4] =
                    make_uint4(f2tf(pa[it].x), f2tf(pa[it].y), f2tf(pa[it].z), f2tf(pa[it].w));
                *(uint4*)&bsw[(f >> 5) * BSTR + (f & 31) * 4] =
                    make_uint4(f2tf(pb[it].x), f2tf(pb[it].y), f2tf(pb[it].z), f2tf(pb[it].w));
            }
            __syncthreads();
        }
    }

#pragma unroll
    for (int mi = 0; mi < 4; mi++) {
#pragma unroll
        for (int nj = 0; nj < 4; nj++) {
            int col = n0 + wn + 8 * nj + 2 * t;
            float b0v = bias[col], b1v = bias[col + 1];
            int row = m0 + wm + 16 * mi + g;
            *(float2*)&Y[(size_t)row * N + col] =
                make_float2(acc[mi][nj][0] + b0v, acc[mi][nj][1] + b1v);
            *(float2*)&Y[(size_t)(row + 8) * N + col] =
                make_float2(acc[mi][nj][2] + b0v, acc[mi][nj][3] + b1v);
        }
    }
}

// ---------------------------------------------------------------------------
// Flash attention v3: BR=256 (8 warps x M=32), Bc=64.
// Q in registers (ldmatrix once, smem recycled). K/V via cp.async double
// buffer (raw fp32; cvt.rna.tf32 on fragment regs). P transposed S->A-frag
// layout via shfl (no smem round-trip).
// ---------------------------------------------------------------------------
#define BR 256
#define BC 64
#define QSTR 68
#define KSTR 68
#define VSTR 72
#define KV_STAGE_WORDS (64 * KSTR + 64 * VSTR)       // 8960
#define ATTN_SMEM (2 * KV_STAGE_WORDS * 4)           // 71680 B (Q stage fits inside)

__global__ __launch_bounds__(256, 1)
void flash_mma(const float* __restrict__ gq, const float* __restrict__ gk,
               const float* __restrict__ gv, float* __restrict__ go) {
    extern __shared__ uint32_t sh[];

    const int tid = threadIdx.x;
    const int lane = tid & 31;
    const int g = lane >> 2, t = lane & 3;
    const int wid = tid >> 5;
    const int r0 = wid * 32;
    const int qt = blockIdx.x;
    const int bh = blockIdx.y;
    const int b = bh >> 4, h = bh & 15;
    const int qbase = qt * BR;
    const size_t rowbase = (size_t)b * SLEN;
    const float scale = 0.125f;

    // ---- Stage Q into smem (tf32, pre-scaled), ldmatrix to regs, free smem
#pragma unroll
    for (int it = 0; it < 16; it++) {
        int f = tid + it * 256;
        int row = f >> 4, c4 = (f & 15) * 4;
        float4 qv = *(const float4*)&gq[(rowbase + qbase + row) * EMB + h * DHEAD + c4];
        *(uint4*)&sh[row * QSTR + c4] =
            make_uint4(f2tf(qv.x * scale), f2tf(qv.y * scale),
                       f2tf(qv.z * scale), f2tf(qv.w * scale));
    }
    __syncthreads();

    uint32_t qf[2][8][4];
#pragma unroll
    for (int mt = 0; mt < 2; mt++)
#pragma unroll
        for (int kd = 0; kd < 8; kd++)
            ldm4(qf[mt][kd],
                 smaddr(&sh[(r0 + 16 * mt + (lane & 15)) * QSTR + kd * 8 + (lane >> 4) * 4]));
    __syncthreads();   // Q smem region now reusable for K/V

    // ---- K/V cp.async double buffer
    const uint32_t shbase = smaddr(sh);
    auto issue_kv = [&](int stage, int kt) {
        uint32_t kbase = shbase + (uint32_t)(stage * KV_STAGE_WORDS) * 4;
        uint32_t vbase = kbase + 64 * KSTR * 4;
#pragma unroll
        for (int i2 = 0; i2 < 4; i2++) {
            int f = tid + i2 * 256;
            int row = f >> 4, c4 = (f & 15) * 4;
            size_t gidx = (rowbase + kt + row) * EMB + h * DHEAD + c4;
            cpasync16(kbase + (uint32_t)(row * KSTR + c4) * 4, &gk[gidx]);
            cpasync16(vbase + (uint32_t)(row * VSTR + c4) * 4, &gv[gidx]);
        }
        asm volatile("cp.async.commit_group;");
    };
    issue_kv(0, 0);

    float o[2][8][4];
#pragma unroll
    for (int mt = 0; mt < 2; mt++)
#pragma unroll
        for (int nd = 0; nd < 8; nd++)
#pragma unroll
            for (int q = 0; q < 4; q++) o[mt][nd][q] = 0.f;
    float mrow[2][2] = {{-1e30f, -1e30f}, {-1e30f, -1e30f}};
    float lrow[2][2] = {{0.f, 0.f}, {0.f, 0.f}};

    const int brow = (lane & 7) + ((lane >> 4) << 3);
    const int bchk = ((lane >> 3) & 1) * 4;
    const int srcA = (lane & 0x1C) + (t >> 1);
    const int srcB = srcA + 2;

    for (int it = 0; it < SLEN / BC; it++) {
        const int stage = it & 1;
        asm volatile("cp.async.wait_group 0;");
        __syncthreads();
        if (it + 1 < SLEN / BC) issue_kv(stage ^ 1, (it + 1) * BC);

        const uint32_t* Ks = sh + stage * KV_STAGE_WORDS;
        const uint32_t* Vs = Ks + 64 * KSTR;

        // ---- S = Q K^T  (32 x 64 per warp)
        float s[2][8][4];
#pragma unroll
        for (int mt = 0; mt < 2; mt++)
#pragma unroll
            for (int nt = 0; nt < 8; nt++)
#pragma unroll
                for (int q = 0; q < 4; q++) s[mt][nt][q] = 0.f;

#pragma unroll
        for (int kd = 0; kd < 8; kd++) {
#pragma unroll
            for (int jj = 0; jj < 4; jj++) {
                uint32_t bb[4];
                ldm4(bb, smaddr(&Ks[(jj * 16 + brow) * KSTR + kd * 8 + bchk]));
#pragma unroll
                for (int q = 0; q < 4; q++) bb[q] = f2tf(__uint_as_float(bb[q]));
#pragma unroll
                for (int mt = 0; mt < 2; mt++) {
                    mma8(s[mt][2 * jj],     qf[mt][kd], bb[0], bb[1]);
                    mma8(s[mt][2 * jj + 1], qf[mt][kd], bb[2], bb[3]);
                }
            }
        }

        // ---- online softmax (4 row groups: mt x {g, g+8})
#pragma unroll
        for (int mt = 0; mt < 2; mt++) {
            float rmax0 = -1e30f, rmax1 = -1e30f;
#pragma unroll
            for (int nt = 0; nt < 8; nt++) {
                rmax0 = fmaxf(rmax0, fmaxf(s[mt][nt][0], s[mt][nt][1]));
                rmax1 = fmaxf(rmax1, fmaxf(s[mt][nt][2], s[mt][nt][3]));
            }
            rmax0 = fmaxf(rmax0, __shfl_xor_sync(0xffffffffu, rmax0, 1));
            rmax0 = fmaxf(rmax0, __shfl_xor_sync(0xffffffffu, rmax0, 2));
            rmax1 = fmaxf(rmax1, __shfl_xor_sync(0xffffffffu, rmax1, 1));
            rmax1 = fmaxf(rmax1, __shfl_xor_sync(0xffffffffu, rmax1, 2));
            float mn0 = fmaxf(mrow[mt][0], rmax0);
            float mn1 = fmaxf(mrow[mt][1], rmax1);
            float cor0 = __expf(mrow[mt][0] - mn0);
            float cor1 = __expf(mrow[mt][1] - mn1);
            mrow[mt][0] = mn0; mrow[mt][1] = mn1;
            float sum0 = 0.f, sum1 = 0.f;
#pragma unroll
            for (int nt = 0; nt < 8; nt++) {
                s[mt][nt][0] = __expf(s[mt][nt][0] - mn0);
                s[mt][nt][1] = __expf(s[mt][nt][1] - mn0);
                s[mt][nt][2] = __expf(s[mt][nt][2] - mn1);
                s[mt][nt][3] = __expf(s[mt][nt][3] - mn1);
                sum0 += s[mt][nt][0] + s[mt][nt][1];
                sum1 += s[mt][nt][2] + s[mt][nt][3];
            }
            sum0 += __shfl_xor_sync(0xffffffffu, sum0, 1);
            sum0 += __shfl_xor_sync(0xffffffffu, sum0, 2);
            sum1 += __shfl_xor_sync(0xffffffffu, sum1, 1);
            sum1 += __shfl_xor_sync(0xffffffffu, sum1, 2);
            lrow[mt][0] = lrow[mt][0] * cor0 + sum0;
            lrow[mt][1] = lrow[mt][1] * cor1 + sum1;
#pragma unroll
            for (int nd = 0; nd < 8; nd++) {
                o[mt][nd][0] *= cor0; o[mt][nd][1] *= cor0;
                o[mt][nd][2] *= cor1; o[mt][nd][3] *= cor1;
            }
        }

        // ---- transpose P: C-layout -> A-frag layout, in place (shfl)
#pragma unroll
        for (int mt = 0; mt < 2; mt++) {
#pragma unroll
            for (int kk = 0; kk < 8; kk++) {
                float s0 = s[mt][kk][0], s1 = s[mt][kk][1];
                float s2 = s[mt][kk][2], s3 = s[mt][kk][3];
                float x0 = __shfl_sync(0xffffffffu, s0, srcA);
                float x1 = __shfl_sync(0xffffffffu, s1, srcA);
                float x2 = __shfl_sync(0xffffffffu, s2, srcA);
                float x3 = __shfl_sync(0xffffffffu, s3, srcA);
                float y0 = __shfl_sync(0xffffffffu, s0, srcB);
                float y1 = __shfl_sync(0xffffffffu, s1, srcB);
                float y2 = __shfl_sync(0xffffffffu, s2, srcB);
                float y3 = __shfl_sync(0xffffffffu, s3, srcB);
                bool odd = (t & 1);
                s[mt][kk][0] = __uint_as_float(f2tf(odd ? x1 : x0));
                s[mt][kk][1] = __uint_as_float(f2tf(odd ? x3 : x2));
                s[mt][kk][2] = __uint_as_float(f2tf(odd ? y1 : y0));
                s[mt][kk][3] = __uint_as_float(f2tf(odd ? y3 : y2));
            }
        }

        // ---- O += P V  (32 x 64 per warp)
#pragma unroll
        for (int kk = 0; kk < 8; kk++) {
#pragma unroll
            for (int nd = 0; nd < 8; nd++) {
                uint32_t v0 = f2tf(__uint_as_float(Vs[(kk * 8 + t) * VSTR + nd * 8 + g]));
                uint32_t v1 = f2tf(__uint_as_float(Vs[(kk * 8 + t + 4) * VSTR + nd * 8 + g]));
#pragma unroll
                for (int mt = 0; mt < 2; mt++) {
                    uint32_t ap[4] = {__float_as_uint(s[mt][kk][0]),
                                      __float_as_uint(s[mt][kk][1]),
                                      __float_as_uint(s[mt][kk][2]),
                                      __float_as_uint(s[mt][kk][3])};
                    mma8(o[mt][nd], ap, v0, v1);
                }
            }
        }
    }

    // ---- normalize + write
#pragma unroll
    for (int mt = 0; mt < 2; mt++) {
        float inv0 = 1.f / lrow[mt][0], inv1 = 1.f / lrow[mt][1];
#pragma unroll
        for (int nd = 0; nd < 8; nd++) {
            int col = h * DHEAD + nd * 8 + 2 * t;
            size_t row = rowbase + qbase + r0 + 16 * mt + g;
            *(float2*)&go[row * EMB + col] =
                make_float2(o[mt][nd][0] * inv0, o[mt][nd][1] * inv0);
            *(float2*)&go[(row + 8) * EMB + col] =
                make_float2(o[mt][nd][2] * inv1, o[mt][nd][3] * inv1);
        }
    }
}

// ---------------------------------------------------------------------------
extern "C" void kernel_launch(void* const* d_in, const int* in_sizes, int n_in,
                              void* d_out, int out_size) {
    const float* query = (const float*)d_in[0];
    const float* key   = (const float*)d_in[1];
    const float* value = (const float*)d_in[2];
    const float* Wq    = (const float*)d_in[3];
    const float* Wk    = (const float*)d_in[4];
    const float* Wv    = (const float*)d_in[5];
    const float* Wo    = (const float*)d_in[6];
    const float* Bq    = (const float*)d_in[7];
    const float* Bk    = (const float*)d_in[8];
    const float* Bv    = (const float*)d_in[9];
    const float* Bo    = (const float*)d_in[10];

    float *q, *k, *v, *attn;
    cudaGetSymbolAddress((void**)&q,    g_q);
    cudaGetSymbolAddress((void**)&k,    g_k);
    cudaGetSymbolAddress((void**)&v,    g_v);
    cudaGetSymbolAddress((void**)&attn, g_attn);

    cudaFuncSetAttribute(gemm_tf32, cudaFuncAttributeMaxDynamicSharedMemorySize, GEMM_SMEM);
    cudaFuncSetAttribute(flash_mma, cudaFuncAttributeMaxDynamicSharedMemorySize, ATTN_SMEM);

    dim3 gblk(256);
    dim3 ggrid(EMB / 128, MTOT / 128);   // (8, 32)

    gemm_tf32<<<ggrid, gblk, GEMM_SMEM>>>(query, Wq, Bq, q, MTOT, EMB, EMB);
    gemm_tf32<<<ggrid, gblk, GEMM_SMEM>>>(key,   Wk, Bk, k, MTOT, EMB, EMB);
    gemm_tf32<<<ggrid, gblk, GEMM_SMEM>>>(value, Wv, Bv, v, MTOT, EMB, EMB);

    flash_mma<<<dim3(SLEN / BR, BATCH * HEADS), gblk, ATTN_SMEM>>>(q, k, v, attn);

    gemm_tf32<<<ggrid, gblk, GEMM_SMEM>>>(attn, Wo, Bo, (float*)d_out, MTOT, EMB, EMB);
}

// round 4
// speedup vs baseline: 3.3184x; 1.0815x over previous
#include <cuda_runtime.h>
#include <cstdint>

#define EMB 1024
#define BATCH 2
#define SLEN 2048
#define HEADS 16
#define DHEAD 64
#define MTOT (BATCH * SLEN)   // 4096

__device__ float g_q[MTOT * EMB];
__device__ float g_k[MTOT * EMB];
__device__ float g_v[MTOT * EMB];
__device__ float g_attn[MTOT * EMB];

// ---------------------------------------------------------------------------
// tf32 mma helpers (m16n8k8, row.col, f32 accumulate)
//   A: a0=(g,t) a1=(g+8,t) a2=(g,t+4) a3=(g+8,t+4)   (g=lane>>2, t=lane&3)
//   B: b0=(t,g) b1=(t+4,g)
//   C: c0=(g,2t) c1=(g,2t+1) c2=(g+8,2t) c3=(g+8,2t+1)
// ---------------------------------------------------------------------------
__device__ __forceinline__ uint32_t f2tf(float f) {
    uint32_t u; asm("cvt.rna.tf32.f32 %0, %1;" : "=r"(u) : "f"(f)); return u;
}
__device__ __forceinline__ uint32_t smaddr(const void* p) {
    return (uint32_t)__cvta_generic_to_shared(p);
}
__device__ __forceinline__ void ldm4(uint32_t a[4], uint32_t addr) {
    asm volatile("ldmatrix.sync.aligned.m8n8.x4.shared.b16 {%0,%1,%2,%3}, [%4];"
                 : "=r"(a[0]), "=r"(a[1]), "=r"(a[2]), "=r"(a[3]) : "r"(addr));
}
__device__ __forceinline__ void mma8(float c[4], const uint32_t a[4],
                                     uint32_t b0, uint32_t b1) {
    asm volatile(
        "mma.sync.aligned.m16n8k8.row.col.f32.tf32.tf32.f32 "
        "{%0,%1,%2,%3}, {%4,%5,%6,%7}, {%8,%9}, {%0,%1,%2,%3};"
        : "+f"(c[0]), "+f"(c[1]), "+f"(c[2]), "+f"(c[3])
        : "r"(a[0]), "r"(a[1]), "r"(a[2]), "r"(a[3]), "r"(b0), "r"(b1));
}
__device__ __forceinline__ void cpasync16(uint32_t saddr, const void* gaddr) {
    asm volatile("cp.async.cg.shared.global [%0], [%1], 16;" :: "r"(saddr), "l"(gaddr));
}

// ---------------------------------------------------------------------------
// GEMM core: Y[m0:+128, n0:+128] = X*W + bias. 3-stage cp.async, BK=32,
// 256 threads, fragment-side tf32 cvt. Optionally round output to tf32.
// ---------------------------------------------------------------------------
#define ASTR 36
#define BSTR 136
#define A_WORDS (128 * ASTR)                 // 4608
#define B_WORDS (32 * BSTR)                  // 4352
#define STAGE_WORDS (A_WORDS + B_WORDS)      // 8960
#define GEMM_SMEM (3 * STAGE_WORDS * 4)      // 107520 B

__device__ __forceinline__
void gemm_core(const float* __restrict__ X, const float* __restrict__ W,
               const float* __restrict__ bias, float* __restrict__ Y,
               int m0, int n0, int N, int K, int round_out, uint32_t* sh) {
    const int tid = threadIdx.x;
    const int lane = tid & 31;
    const int g = lane >> 2, t = lane & 3;
    const int wid = tid >> 5;
    const int wm = (wid >> 2) * 64;
    const int wn = (wid & 3) * 32;

    const float* Aptr = X + (size_t)m0 * K;
    const float* Bptr = W + n0;
    const uint32_t sbase = smaddr(sh);

    auto issue = [&](int slot, int k0) {
        uint32_t abase = sbase + (uint32_t)slot * (STAGE_WORDS * 4);
        uint32_t bbase = abase + A_WORDS * 4;
#pragma unroll
        for (int i = 0; i < 4; i++) {
            int f = tid + i * 256;
            cpasync16(abase + (uint32_t)((f >> 3) * ASTR + (f & 7) * 4) * 4,
                      &Aptr[(size_t)(f >> 3) * K + k0 + (f & 7) * 4]);
            cpasync16(bbase + (uint32_t)((f >> 5) * BSTR + (f & 31) * 4) * 4,
                      &Bptr[(size_t)(k0 + (f >> 5)) * N + (f & 31) * 4]);
        }
        asm volatile("cp.async.commit_group;");
    };

    issue(0, 0);
    issue(1, 32);

    float acc[4][4][4];
#pragma unroll
    for (int i = 0; i < 4; i++)
#pragma unroll
        for (int j = 0; j < 4; j++)
#pragma unroll
            for (int q = 0; q < 4; q++) acc[i][j][q] = 0.f;

    const int nit = K / 32;
    for (int it = 0; it < nit; it++) {
        asm volatile("cp.async.wait_group 1;");
        __syncthreads();
        if (it + 2 < nit) issue((it + 2) % 3, (it + 2) * 32);
        else asm volatile("cp.async.commit_group;");

        const uint32_t* as = sh + (it % 3) * STAGE_WORDS;
        const uint32_t* bs = as + A_WORDS;
#pragma unroll
        for (int ks = 0; ks < 4; ks++) {
            const int k0 = ks * 8;
            uint32_t a[4][4];
#pragma unroll
            for (int mi = 0; mi < 4; mi++) {
                ldm4(a[mi], smaddr(&as[(wm + 16 * mi + (lane & 15)) * ASTR +
                                       k0 + (lane >> 4) * 4]));
#pragma unroll
                for (int q = 0; q < 4; q++)
                    a[mi][q] = f2tf(__uint_as_float(a[mi][q]));
            }
            uint32_t b[4][2];
#pragma unroll
            for (int nj = 0; nj < 4; nj++) {
                b[nj][0] = f2tf(__uint_as_float(bs[(k0 + t) * BSTR + wn + 8 * nj + g]));
                b[nj][1] = f2tf(__uint_as_float(bs[(k0 + t + 4) * BSTR + wn + 8 * nj + g]));
            }
#pragma unroll
            for (int mi = 0; mi < 4; mi++)
#pragma unroll
                for (int nj = 0; nj < 4; nj++)
                    mma8(acc[mi][nj], a[mi], b[nj][0], b[nj][1]);
        }
    }

#pragma unroll
    for (int mi = 0; mi < 4; mi++) {
#pragma unroll
        for (int nj = 0; nj < 4; nj++) {
            int col = n0 + wn + 8 * nj + 2 * t;
            float b0v = bias[col], b1v = bias[col + 1];
            int row = m0 + wm + 16 * mi + g;
            float o00 = acc[mi][nj][0] + b0v, o01 = acc[mi][nj][1] + b1v;
            float o10 = acc[mi][nj][2] + b0v, o11 = acc[mi][nj][3] + b1v;
            if (round_out) {
                o00 = __uint_as_float(f2tf(o00)); o01 = __uint_as_float(f2tf(o01));
                o10 = __uint_as_float(f2tf(o10)); o11 = __uint_as_float(f2tf(o11));
            }
            *(float2*)&Y[(size_t)row * N + col] = make_float2(o00, o01);
            *(float2*)&Y[(size_t)(row + 8) * N + col] = make_float2(o10, o11);
        }
    }
}

// Fused QKV projections: grid.z selects {query,key,value}. Outputs tf32-rounded.
__global__ __launch_bounds__(256, 2)
void qkv_gemm(const float* __restrict__ q, const float* __restrict__ k,
              const float* __restrict__ v,
              const float* __restrict__ Wq, const float* __restrict__ Wk,
              const float* __restrict__ Wv,
              const float* __restrict__ Bq, const float* __restrict__ Bk,
              const float* __restrict__ Bv,
              float* __restrict__ oq, float* __restrict__ ok, float* __restrict__ ov) {
    extern __shared__ uint32_t sh[];
    const float *X, *W, *B;
    float* Y;
    if (blockIdx.z == 0)      { X = q; W = Wq; B = Bq; Y = oq; }
    else if (blockIdx.z == 1) { X = k; W = Wk; B = Bk; Y = ok; }
    else                      { X = v; W = Wv; B = Bv; Y = ov; }
    gemm_core(X, W, B, Y, blockIdx.y * 128, blockIdx.x * 128, EMB, EMB, 1, sh);
}

__global__ __launch_bounds__(256, 2)
void out_gemm(const float* __restrict__ X, const float* __restrict__ W,
              const float* __restrict__ B, float* __restrict__ Y) {
    extern __shared__ uint32_t sh[];
    gemm_core(X, W, B, Y, blockIdx.y * 128, blockIdx.x * 128, EMB, EMB, 0, sh);
}

// ---------------------------------------------------------------------------
// Flash attention v4: 128 threads (4 warps x M=32 rows), BR=128, Bc=64.
// Inputs pre-rounded to tf32 -> no fragment cvts. Q in registers. K/V via
// 3-stage cp.async pipeline, one __syncthreads per iter. P transposed
// C-layout -> A-frag layout via shfl. 2 CTAs/SM.
// ---------------------------------------------------------------------------
#define BR 128
#define BC 64
#define QSTR 68
#define KSTR 68
#define VSTR 72
#define KV_STAGE_WORDS (64 * KSTR + 64 * VSTR)   // 8960
#define ATTN_SMEM (3 * KV_STAGE_WORDS * 4)       // 107520 B

__global__ __launch_bounds__(128, 2)
void flash_mma(const float* __restrict__ gq, const float* __restrict__ gk,
               const float* __restrict__ gv, float* __restrict__ go) {
    extern __shared__ uint32_t sh[];

    const int tid = threadIdx.x;
    const int lane = tid & 31;
    const int g = lane >> 2, t = lane & 3;
    const int wid = tid >> 5;
    const int r0 = wid * 32;
    const int qt = blockIdx.x;
    const int bh = blockIdx.y;
    const int b = bh >> 4, h = bh & 15;
    const int qbase = qt * BR;
    const size_t rowbase = (size_t)b * SLEN;
    const float scale = 0.125f;   // power of 2: preserves tf32 rounding

    // ---- Stage Q (pre-rounded tf32 * 2^-3) into smem, ldmatrix to regs
#pragma unroll
    for (int it = 0; it < 16; it++) {
        int f = tid + it * 128;
        int row = f >> 4, c4 = (f & 15) * 4;
        float4 qv = *(const float4*)&gq[(rowbase + qbase + row) * EMB + h * DHEAD + c4];
        *(float4*)&sh[row * QSTR + c4] =
            make_float4(qv.x * scale, qv.y * scale, qv.z * scale, qv.w * scale);
    }
    __syncthreads();

    uint32_t qf[2][8][4];
#pragma unroll
    for (int mt = 0; mt < 2; mt++)
#pragma unroll
        for (int kd = 0; kd < 8; kd++)
            ldm4(qf[mt][kd],
                 smaddr(&sh[(r0 + 16 * mt + (lane & 15)) * QSTR + kd * 8 + (lane >> 4) * 4]));
    __syncthreads();   // Q region now reusable as K/V stage 0

    const uint32_t shbase = smaddr(sh);
    auto issue_kv = [&](int slot, int kt) {
        uint32_t kbase = shbase + (uint32_t)(slot * KV_STAGE_WORDS) * 4;
        uint32_t vbase = kbase + 64 * KSTR * 4;
#pragma unroll
        for (int i2 = 0; i2 < 8; i2++) {
            int f = tid + i2 * 128;
            int row = f >> 4, c4 = (f & 15) * 4;
            size_t gidx = (rowbase + kt + row) * EMB + h * DHEAD + c4;
            cpasync16(kbase + (uint32_t)(row * KSTR + c4) * 4, &gk[gidx]);
            cpasync16(vbase + (uint32_t)(row * VSTR + c4) * 4, &gv[gidx]);
        }
        asm volatile("cp.async.commit_group;");
    };
    issue_kv(0, 0);
    issue_kv(1, BC);

    float o[2][8][4];
#pragma unroll
    for (int mt = 0; mt < 2; mt++)
#pragma unroll
        for (int nd = 0; nd < 8; nd++)
#pragma unroll
            for (int q = 0; q < 4; q++) o[mt][nd][q] = 0.f;
    float mrow[2][2] = {{-1e30f, -1e30f}, {-1e30f, -1e30f}};
    float lrow[2][2] = {{0.f, 0.f}, {0.f, 0.f}};

    const int brow = (lane & 7) + ((lane >> 4) << 3);
    const int bchk = ((lane >> 3) & 1) * 4;
    const int srcA = (lane & 0x1C) + (t >> 1);
    const int srcB = srcA + 2;

    const int NIT = SLEN / BC;   // 32
    for (int it = 0; it < NIT; it++) {
        asm volatile("cp.async.wait_group 1;");
        __syncthreads();
        if (it + 2 < NIT) issue_kv((it + 2) % 3, (it + 2) * BC);
        else asm volatile("cp.async.commit_group;");

        const uint32_t* Ks = sh + (it % 3) * KV_STAGE_WORDS;
        const uint32_t* Vs = Ks + 64 * KSTR;

        // ---- S = Q K^T (32 x 64 per warp); K already tf32
        float s[2][8][4];
#pragma unroll
        for (int mt = 0; mt < 2; mt++)
#pragma unroll
            for (int nt = 0; nt < 8; nt++)
#pragma unroll
                for (int q = 0; q < 4; q++) s[mt][nt][q] = 0.f;

#pragma unroll
        for (int kd = 0; kd < 8; kd++) {
#pragma unroll
            for (int jj = 0; jj < 4; jj++) {
                uint32_t bb[4];
                ldm4(bb, smaddr(&Ks[(jj * 16 + brow) * KSTR + kd * 8 + bchk]));
#pragma unroll
                for (int mt = 0; mt < 2; mt++) {
                    mma8(s[mt][2 * jj],     qf[mt][kd], bb[0], bb[1]);
                    mma8(s[mt][2 * jj + 1], qf[mt][kd], bb[2], bb[3]);
                }
            }
        }

        // ---- online softmax (row groups: mt x {g, g+8})
#pragma unroll
        for (int mt = 0; mt < 2; mt++) {
            float rmax0 = -1e30f, rmax1 = -1e30f;
#pragma unroll
            for (int nt = 0; nt < 8; nt++) {
                rmax0 = fmaxf(rmax0, fmaxf(s[mt][nt][0], s[mt][nt][1]));
                rmax1 = fmaxf(rmax1, fmaxf(s[mt][nt][2], s[mt][nt][3]));
            }
            rmax0 = fmaxf(rmax0, __shfl_xor_sync(0xffffffffu, rmax0, 1));
            rmax0 = fmaxf(rmax0, __shfl_xor_sync(0xffffffffu, rmax0, 2));
            rmax1 = fmaxf(rmax1, __shfl_xor_sync(0xffffffffu, rmax1, 1));
            rmax1 = fmaxf(rmax1, __shfl_xor_sync(0xffffffffu, rmax1, 2));
            float mn0 = fmaxf(mrow[mt][0], rmax0);
            float mn1 = fmaxf(mrow[mt][1], rmax1);
            float cor0 = __expf(mrow[mt][0] - mn0);
            float cor1 = __expf(mrow[mt][1] - mn1);
            mrow[mt][0] = mn0; mrow[mt][1] = mn1;
            float sum0 = 0.f, sum1 = 0.f;
#pragma unroll
            for (int nt = 0; nt < 8; nt++) {
                s[mt][nt][0] = __expf(s[mt][nt][0] - mn0);
                s[mt][nt][1] = __expf(s[mt][nt][1] - mn0);
                s[mt][nt][2] = __expf(s[mt][nt][2] - mn1);
                s[mt][nt][3] = __expf(s[mt][nt][3] - mn1);
                sum0 += s[mt][nt][0] + s[mt][nt][1];
                sum1 += s[mt][nt][2] + s[mt][nt][3];
            }
            sum0 += __shfl_xor_sync(0xffffffffu, sum0, 1);
            sum0 += __shfl_xor_sync(0xffffffffu, sum0, 2);
            sum1 += __shfl_xor_sync(0xffffffffu, sum1, 1);
            sum1 += __shfl_xor_sync(0xffffffffu, sum1, 2);
            lrow[mt][0] = lrow[mt][0] * cor0 + sum0;
            lrow[mt][1] = lrow[mt][1] * cor1 + sum1;
#pragma unroll
            for (int nd = 0; nd < 8; nd++) {
                o[mt][nd][0] *= cor0; o[mt][nd][1] *= cor0;
                o[mt][nd][2] *= cor1; o[mt][nd][3] *= cor1;
            }
        }

        // ---- transpose P: C-layout -> A-frag layout (shfl), cvt to tf32
#pragma unroll
        for (int mt = 0; mt < 2; mt++) {
#pragma unroll
            for (int kk = 0; kk < 8; kk++) {
                float s0 = s[mt][kk][0], s1 = s[mt][kk][1];
                float s2 = s[mt][kk][2], s3 = s[mt][kk][3];
                float x0 = __shfl_sync(0xffffffffu, s0, srcA);
                float x1 = __shfl_sync(0xffffffffu, s1, srcA);
                float x2 = __shfl_sync(0xffffffffu, s2, srcA);
                float x3 = __shfl_sync(0xffffffffu, s3, srcA);
                float y0 = __shfl_sync(0xffffffffu, s0, srcB);
                float y1 = __shfl_sync(0xffffffffu, s1, srcB);
                float y2 = __shfl_sync(0xffffffffu, s2, srcB);
                float y3 = __shfl_sync(0xffffffffu, s3, srcB);
                bool odd = (t & 1);
                s[mt][kk][0] = __uint_as_float(f2tf(odd ? x1 : x0));
                s[mt][kk][1] = __uint_as_float(f2tf(odd ? x3 : x2));
                s[mt][kk][2] = __uint_as_float(f2tf(odd ? y1 : y0));
                s[mt][kk][3] = __uint_as_float(f2tf(odd ? y3 : y2));
            }
        }

        // ---- O += P V (V already tf32)
#pragma unroll
        for (int kk = 0; kk < 8; kk++) {
#pragma unroll
            for (int nd = 0; nd < 8; nd++) {
                uint32_t v0 = Vs[(kk * 8 + t) * VSTR + nd * 8 + g];
                uint32_t v1 = Vs[(kk * 8 + t + 4) * VSTR + nd * 8 + g];
#pragma unroll
                for (int mt = 0; mt < 2; mt++) {
                    uint32_t ap[4] = {__float_as_uint(s[mt][kk][0]),
                                      __float_as_uint(s[mt][kk][1]),
                                      __float_as_uint(s[mt][kk][2]),
                                      __float_as_uint(s[mt][kk][3])};
                    mma8(o[mt][nd], ap, v0, v1);
                }
            }
        }
    }

    // ---- normalize + write
#pragma unroll
    for (int mt = 0; mt < 2; mt++) {
        float inv0 = 1.f / lrow[mt][0], inv1 = 1.f / lrow[mt][1];
#pragma unroll
        for (int nd = 0; nd < 8; nd++) {
            int col = h * DHEAD + nd * 8 + 2 * t;
            size_t row = rowbase + qbase + r0 + 16 * mt + g;
            *(float2*)&go[row * EMB + col] =
                make_float2(o[mt][nd][0] * inv0, o[mt][nd][1] * inv0);
            *(float2*)&go[(row + 8) * EMB + col] =
                make_float2(o[mt][nd][2] * inv1, o[mt][nd][3] * inv1);
        }
    }
}

// ---------------------------------------------------------------------------
extern "C" void kernel_launch(void* const* d_in, const int* in_sizes, int n_in,
                              void* d_out, int out_size) {
    const float* query = (const float*)d_in[0];
    const float* key   = (const float*)d_in[1];
    const float* value = (const float*)d_in[2];
    const float* Wq    = (const float*)d_in[3];
    const float* Wk    = (const float*)d_in[4];
    const float* Wv    = (const float*)d_in[5];
    const float* Wo    = (const float*)d_in[6];
    const float* Bq    = (const float*)d_in[7];
    const float* Bk    = (const float*)d_in[8];
    const float* Bv    = (const float*)d_in[9];
    const float* Bo    = (const float*)d_in[10];

    float *q, *k, *v, *attn;
    cudaGetSymbolAddress((void**)&q,    g_q);
    cudaGetSymbolAddress((void**)&k,    g_k);
    cudaGetSymbolAddress((void**)&v,    g_v);
    cudaGetSymbolAddress((void**)&attn, g_attn);

    cudaFuncSetAttribute(qkv_gemm, cudaFuncAttributeMaxDynamicSharedMemorySize, GEMM_SMEM);
    cudaFuncSetAttribute(out_gemm, cudaFuncAttributeMaxDynamicSharedMemorySize, GEMM_SMEM);
    cudaFuncSetAttribute(flash_mma, cudaFuncAttributeMaxDynamicSharedMemorySize, ATTN_SMEM);

    qkv_gemm<<<dim3(EMB / 128, MTOT / 128, 3), 256, GEMM_SMEM>>>(
        query, key, value, Wq, Wk, Wv, Bq, Bk, Bv, q, k, v);

    flash_mma<<<dim3(SLEN / BR, BATCH * HEADS), 128, ATTN_SMEM>>>(q, k, v, attn);

    out_gemm<<<dim3(EMB / 128, MTOT / 128), 256, GEMM_SMEM>>>(attn, Wo, Bo, (float*)d_out);
}

// round 5
// speedup vs baseline: 3.3199x; 1.0005x over previous
#include <cuda_runtime.h>
#include <cstdint>

#define EMB 1024
#define BATCH 2
#define SLEN 2048
#define HEADS 16
#define DHEAD 64
#define MTOT (BATCH * SLEN)   // 4096

__device__ float g_q[MTOT * EMB];
__device__ float g_k[MTOT * EMB];
__device__ float g_v[MTOT * EMB];
__device__ float g_attn[MTOT * EMB];

// ---------------------------------------------------------------------------
// tf32 mma helpers (m16n8k8, row.col, f32 accumulate)
//   A: a0=(g,t) a1=(g+8,t) a2=(g,t+4) a3=(g+8,t+4)   (g=lane>>2, t=lane&3)
//   B: b0=(t,g) b1=(t+4,g)
//   C: c0=(g,2t) c1=(g,2t+1) c2=(g+8,2t) c3=(g+8,2t+1)
// ---------------------------------------------------------------------------
__device__ __forceinline__ uint32_t f2tf(float f) {
    uint32_t u; asm("cvt.rna.tf32.f32 %0, %1;" : "=r"(u) : "f"(f)); return u;
}
__device__ __forceinline__ uint32_t smaddr(const void* p) {
    return (uint32_t)__cvta_generic_to_shared(p);
}
__device__ __forceinline__ void ldm4(uint32_t a[4], uint32_t addr) {
    asm volatile("ldmatrix.sync.aligned.m8n8.x4.shared.b16 {%0,%1,%2,%3}, [%4];"
                 : "=r"(a[0]), "=r"(a[1]), "=r"(a[2]), "=r"(a[3]) : "r"(addr));
}
__device__ __forceinline__ void mma8(float c[4], const uint32_t a[4],
                                     uint32_t b0, uint32_t b1) {
    asm volatile(
        "mma.sync.aligned.m16n8k8.row.col.f32.tf32.tf32.f32 "
        "{%0,%1,%2,%3}, {%4,%5,%6,%7}, {%8,%9}, {%0,%1,%2,%3};"
        : "+f"(c[0]), "+f"(c[1]), "+f"(c[2]), "+f"(c[3])
        : "r"(a[0]), "r"(a[1]), "r"(a[2]), "r"(a[3]), "r"(b0), "r"(b1));
}
__device__ __forceinline__ void cpasync16(uint32_t saddr, const void* gaddr) {
    asm volatile("cp.async.cg.shared.global [%0], [%1], 16;" :: "r"(saddr), "l"(gaddr));
}

// ---------------------------------------------------------------------------
// GEMM core: Y[m0:+128, n0:+128] = X*W + bias. 3-stage cp.async, BK=32,
// 256 threads, fragment-side tf32 cvt. Optionally round output to tf32.
// ---------------------------------------------------------------------------
#define ASTR 36
#define BSTR 136
#define A_WORDS (128 * ASTR)                 // 4608
#define B_WORDS (32 * BSTR)                  // 4352
#define STAGE_WORDS (A_WORDS + B_WORDS)      // 8960
#define GEMM_SMEM (3 * STAGE_WORDS * 4)      // 107520 B

__device__ __forceinline__
void gemm_core(const float* __restrict__ X, const float* __restrict__ W,
               const float* __restrict__ bias, float* __restrict__ Y,
               int m0, int n0, int N, int K, int round_out, uint32_t* sh) {
    const int tid = threadIdx.x;
    const int lane = tid & 31;
    const int g = lane >> 2, t = lane & 3;
    const int wid = tid >> 5;
    const int wm = (wid >> 2) * 64;
    const int wn = (wid & 3) * 32;

    const float* Aptr = X + (size_t)m0 * K;
    const float* Bptr = W + n0;
    const uint32_t sbase = smaddr(sh);

    auto issue = [&](int slot, int k0) {
        uint32_t abase = sbase + (uint32_t)slot * (STAGE_WORDS * 4);
        uint32_t bbase = abase + A_WORDS * 4;
#pragma unroll
        for (int i = 0; i < 4; i++) {
            int f = tid + i * 256;
            cpasync16(abase + (uint32_t)((f >> 3) * ASTR + (f & 7) * 4) * 4,
                      &Aptr[(size_t)(f >> 3) * K + k0 + (f & 7) * 4]);
            cpasync16(bbase + (uint32_t)((f >> 5) * BSTR + (f & 31) * 4) * 4,
                      &Bptr[(size_t)(k0 + (f >> 5)) * N + (f & 31) * 4]);
        }
        asm volatile("cp.async.commit_group;");
    };

    issue(0, 0);
    issue(1, 32);

    float acc[4][4][4];
#pragma unroll
    for (int i = 0; i < 4; i++)
#pragma unroll
        for (int j = 0; j < 4; j++)
#pragma unroll
            for (int q = 0; q < 4; q++) acc[i][j][q] = 0.f;

    const int nit = K / 32;
    for (int it = 0; it < nit; it++) {
        asm volatile("cp.async.wait_group 1;");
        __syncthreads();
        if (it + 2 < nit) issue((it + 2) % 3, (it + 2) * 32);
        else asm volatile("cp.async.commit_group;");

        const uint32_t* as = sh + (it % 3) * STAGE_WORDS;
        const uint32_t* bs = as + A_WORDS;
#pragma unroll
        for (int ks = 0; ks < 4; ks++) {
            const int k0 = ks * 8;
            uint32_t a[4][4];
#pragma unroll
            for (int mi = 0; mi < 4; mi++) {
                ldm4(a[mi], smaddr(&as[(wm + 16 * mi + (lane & 15)) * ASTR +
                                       k0 + (lane >> 4) * 4]));
#pragma unroll
                for (int q = 0; q < 4; q++)
                    a[mi][q] = f2tf(__uint_as_float(a[mi][q]));
            }
            uint32_t b[4][2];
#pragma unroll
            for (int nj = 0; nj < 4; nj++) {
                b[nj][0] = f2tf(__uint_as_float(bs[(k0 + t) * BSTR + wn + 8 * nj + g]));
                b[nj][1] = f2tf(__uint_as_float(bs[(k0 + t + 4) * BSTR + wn + 8 * nj + g]));
            }
#pragma unroll
            for (int mi = 0; mi < 4; mi++)
#pragma unroll
                for (int nj = 0; nj < 4; nj++)
                    mma8(acc[mi][nj], a[mi], b[nj][0], b[nj][1]);
        }
    }

#pragma unroll
    for (int mi = 0; mi < 4; mi++) {
#pragma unroll
        for (int nj = 0; nj < 4; nj++) {
            int col = n0 + wn + 8 * nj + 2 * t;
            float b0v = bias[col], b1v = bias[col + 1];
            int row = m0 + wm + 16 * mi + g;
            float o00 = acc[mi][nj][0] + b0v, o01 = acc[mi][nj][1] + b1v;
            float o10 = acc[mi][nj][2] + b0v, o11 = acc[mi][nj][3] + b1v;
            if (round_out) {
                o00 = __uint_as_float(f2tf(o00)); o01 = __uint_as_float(f2tf(o01));
                o10 = __uint_as_float(f2tf(o10)); o11 = __uint_as_float(f2tf(o11));
            }
            *(float2*)&Y[(size_t)row * N + col] = make_float2(o00, o01);
            *(float2*)&Y[(size_t)(row + 8) * N + col] = make_float2(o10, o11);
        }
    }
}

// Fused QKV projections: grid.z selects {query,key,value}. Outputs tf32-rounded.
__global__ __launch_bounds__(256, 2)
void qkv_gemm(const float* __restrict__ q, const float* __restrict__ k,
              const float* __restrict__ v,
              const float* __restrict__ Wq, const float* __restrict__ Wk,
              const float* __restrict__ Wv,
              const float* __restrict__ Bq, const float* __restrict__ Bk,
              const float* __restrict__ Bv,
              float* __restrict__ oq, float* __restrict__ ok, float* __restrict__ ov) {
    extern __shared__ uint32_t sh[];
    const float *X, *W, *B;
    float* Y;
    if (blockIdx.z == 0)      { X = q; W = Wq; B = Bq; Y = oq; }
    else if (blockIdx.z == 1) { X = k; W = Wk; B = Bk; Y = ok; }
    else                      { X = v; W = Wv; B = Bv; Y = ov; }
    gemm_core(X, W, B, Y, blockIdx.y * 128, blockIdx.x * 128, EMB, EMB, 1, sh);
}

__global__ __launch_bounds__(256, 2)
void out_gemm(const float* __restrict__ X, const float* __restrict__ W,
              const float* __restrict__ B, float* __restrict__ Y) {
    extern __shared__ uint32_t sh[];
    gemm_core(X, W, B, Y, blockIdx.y * 128, blockIdx.x * 128, EMB, EMB, 0, sh);
}

// ---------------------------------------------------------------------------
// Flash attention v4: 128 threads (4 warps x M=32 rows), BR=128, Bc=64.
// Inputs pre-rounded to tf32 -> no fragment cvts. Q in registers. K/V via
// 3-stage cp.async pipeline, one __syncthreads per iter. P transposed
// C-layout -> A-frag layout via shfl. 2 CTAs/SM.
// ---------------------------------------------------------------------------
#define BR 128
#define BC 64
#define QSTR 68
#define KSTR 68
#define VSTR 72
#define KV_STAGE_WORDS (64 * KSTR + 64 * VSTR)   // 8960
#define ATTN_SMEM (3 * KV_STAGE_WORDS * 4)       // 107520 B

__global__ __launch_bounds__(128, 2)
void flash_mma(const float* __restrict__ gq, const float* __restrict__ gk,
               const float* __restrict__ gv, float* __restrict__ go) {
    extern __shared__ uint32_t sh[];

    const int tid = threadIdx.x;
    const int lane = tid & 31;
    const int g = lane >> 2, t = lane & 3;
    const int wid = tid >> 5;
    const int r0 = wid * 32;
    const int qt = blockIdx.x;
    const int bh = blockIdx.y;
    const int b = bh >> 4, h = bh & 15;
    const int qbase = qt * BR;
    const size_t rowbase = (size_t)b * SLEN;
    const float scale = 0.125f;   // power of 2: preserves tf32 rounding

    // ---- Stage Q (pre-rounded tf32 * 2^-3) into smem, ldmatrix to regs
#pragma unroll
    for (int it = 0; it < 16; it++) {
        int f = tid + it * 128;
        int row = f >> 4, c4 = (f & 15) * 4;
        float4 qv = *(const float4*)&gq[(rowbase + qbase + row) * EMB + h * DHEAD + c4];
        *(float4*)&sh[row * QSTR + c4] =
            make_float4(qv.x * scale, qv.y * scale, qv.z * scale, qv.w * scale);
    }
    __syncthreads();

    uint32_t qf[2][8][4];
#pragma unroll
    for (int mt = 0; mt < 2; mt++)
#pragma unroll
        for (int kd = 0; kd < 8; kd++)
            ldm4(qf[mt][kd],
                 smaddr(&sh[(r0 + 16 * mt + (lane & 15)) * QSTR + kd * 8 + (lane >> 4) * 4]));
    __syncthreads();   // Q region now reusable as K/V stage 0

    const uint32_t shbase = smaddr(sh);
    auto issue_kv = [&](int slot, int kt) {
        uint32_t kbase = shbase + (uint32_t)(slot * KV_STAGE_WORDS) * 4;
        uint32_t vbase = kbase + 64 * KSTR * 4;
#pragma unroll
        for (int i2 = 0; i2 < 8; i2++) {
            int f = tid + i2 * 128;
            int row = f >> 4, c4 = (f & 15) * 4;
            size_t gidx = (rowbase + kt + row) * EMB + h * DHEAD + c4;
            cpasync16(kbase + (uint32_t)(row * KSTR + c4) * 4, &gk[gidx]);
            cpasync16(vbase + (uint32_t)(row * VSTR + c4) * 4, &gv[gidx]);
        }
        asm volatile("cp.async.commit_group;");
    };
    issue_kv(0, 0);
    issue_kv(1, BC);

    float o[2][8][4];
#pragma unroll
    for (int mt = 0; mt < 2; mt++)
#pragma unroll
        for (int nd = 0; nd < 8; nd++)
#pragma unroll
            for (int q = 0; q < 4; q++) o[mt][nd][q] = 0.f;
    float mrow[2][2] = {{-1e30f, -1e30f}, {-1e30f, -1e30f}};
    float lrow[2][2] = {{0.f, 0.f}, {0.f, 0.f}};

    const int brow = (lane & 7) + ((lane >> 4) << 3);
    const int bchk = ((lane >> 3) & 1) * 4;
    const int srcA = (lane & 0x1C) + (t >> 1);
    const int srcB = srcA + 2;

    const int NIT = SLEN / BC;   // 32
    for (int it = 0; it < NIT; it++) {
        asm volatile("cp.async.wait_group 1;");
        __syncthreads();
        if (it + 2 < NIT) issue_kv((it + 2) % 3, (it + 2) * BC);
        else asm volatile("cp.async.commit_group;");

        const uint32_t* Ks = sh + (it % 3) * KV_STAGE_WORDS;
        const uint32_t* Vs = Ks + 64 * KSTR;

        // ---- S = Q K^T (32 x 64 per warp); K already tf32
        float s[2][8][4];
#pragma unroll
        for (int mt = 0; mt < 2; mt++)
#pragma unroll
            for (int nt = 0; nt < 8; nt++)
#pragma unroll
                for (int q = 0; q < 4; q++) s[mt][nt][q] = 0.f;

#pragma unroll
        for (int kd = 0; kd < 8; kd++) {
#pragma unroll
            for (int jj = 0; jj < 4; jj++) {
                uint32_t bb[4];
                ldm4(bb, smaddr(&Ks[(jj * 16 + brow) * KSTR + kd * 8 + bchk]));
#pragma unroll
                for (int mt = 0; mt < 2; mt++) {
                    mma8(s[mt][2 * jj],     qf[mt][kd], bb[0], bb[1]);
                    mma8(s[mt][2 * jj + 1], qf[mt][kd], bb[2], bb[3]);
                }
            }
        }

        // ---- online softmax (row groups: mt x {g, g+8})
#pragma unroll
        for (int mt = 0; mt < 2; mt++) {
            float rmax0 = -1e30f, rmax1 = -1e30f;
#pragma unroll
            for (int nt = 0; nt < 8; nt++) {
                rmax0 = fmaxf(rmax0, fmaxf(s[mt][nt][0], s[mt][nt][1]));
                rmax1 = fmaxf(rmax1, fmaxf(s[mt][nt][2], s[mt][nt][3]));
            }
            rmax0 = fmaxf(rmax0, __shfl_xor_sync(0xffffffffu, rmax0, 1));
            rmax0 = fmaxf(rmax0, __shfl_xor_sync(0xffffffffu, rmax0, 2));
            rmax1 = fmaxf(rmax1, __shfl_xor_sync(0xffffffffu, rmax1, 1));
            rmax1 = fmaxf(rmax1, __shfl_xor_sync(0xffffffffu, rmax1, 2));
            float mn0 = fmaxf(mrow[mt][0], rmax0);
            float mn1 = fmaxf(mrow[mt][1], rmax1);
            float cor0 = __expf(mrow[mt][0] - mn0);
            float cor1 = __expf(mrow[mt][1] - mn1);
            mrow[mt][0] = mn0; mrow[mt][1] = mn1;
            float sum0 = 0.f, sum1 = 0.f;
#pragma unroll
            for (int nt = 0; nt < 8; nt++) {
                s[mt][nt][0] = __expf(s[mt][nt][0] - mn0);
                s[mt][nt][1] = __expf(s[mt][nt][1] - mn0);
                s[mt][nt][2] = __expf(s[mt][nt][2] - mn1);
                s[mt][nt][3] = __expf(s[mt][nt][3] - mn1);
                sum0 += s[mt][nt][0] + s[mt][nt][1];
                sum1 += s[mt][nt][2] + s[mt][nt][3];
            }
            sum0 += __shfl_xor_sync(0xffffffffu, sum0, 1);
            sum0 += __shfl_xor_sync(0xffffffffu, sum0, 2);
            sum1 += __shfl_xor_sync(0xffffffffu, sum1, 1);
            sum1 += __shfl_xor_sync(0xffffffffu, sum1, 2);
            lrow[mt][0] = lrow[mt][0] * cor0 + sum0;
            lrow[mt][1] = lrow[mt][1] * cor1 + sum1;
#pragma unroll
            for (int nd = 0; nd < 8; nd++) {
                o[mt][nd][0] *= cor0; o[mt][nd][1] *= cor0;
                o[mt][nd][2] *= cor1; o[mt][nd][3] *= cor1;
            }
        }

        // ---- transpose P: C-layout -> A-frag layout (shfl), cvt to tf32
#pragma unroll
        for (int mt = 0; mt < 2; mt++) {
#pragma unroll
            for (int kk = 0; kk < 8; kk++) {
                float s0 = s[mt][kk][0], s1 = s[mt][kk][1];
                float s2 = s[mt][kk][2], s3 = s[mt][kk][3];
                float x0 = __shfl_sync(0xffffffffu, s0, srcA);
                float x1 = __shfl_sync(0xffffffffu, s1, srcA);
                float x2 = __shfl_sync(0xffffffffu, s2, srcA);
                float x3 = __shfl_sync(0xffffffffu, s3, srcA);
                float y0 = __shfl_sync(0xffffffffu, s0, srcB);
                float y1 = __shfl_sync(0xffffffffu, s1, srcB);
                float y2 = __shfl_sync(0xffffffffu, s2, srcB);
                float y3 = __shfl_sync(0xffffffffu, s3, srcB);
                bool odd = (t & 1);
                s[mt][kk][0] = __uint_as_float(f2tf(odd ? x1 : x0));
                s[mt][kk][1] = __uint_as_float(f2tf(odd ? x3 : x2));
                s[mt][kk][2] = __uint_as_float(f2tf(odd ? y1 : y0));
                s[mt][kk][3] = __uint_as_float(f2tf(odd ? y3 : y2));
            }
        }

        // ---- O += P V (V already tf32)
#pragma unroll
        for (int kk = 0; kk < 8; kk++) {
#pragma unroll
            for (int nd = 0; nd < 8; nd++) {
                uint32_t v0 = Vs[(kk * 8 + t) * VSTR + nd * 8 + g];
                uint32_t v1 = Vs[(kk * 8 + t + 4) * VSTR + nd * 8 + g];
#pragma unroll
                for (int mt = 0; mt < 2; mt++) {
                    uint32_t ap[4] = {__float_as_uint(s[mt][kk][0]),
                                      __float_as_uint(s[mt][kk][1]),
                                      __float_as_uint(s[mt][kk][2]),
                                      __float_as_uint(s[mt][kk][3])};
                    mma8(o[mt][nd], ap, v0, v1);
                }
            }
        }
    }

    // ---- normalize + write
#pragma unroll
    for (int mt = 0; mt < 2; mt++) {
        float inv0 = 1.f / lrow[mt][0], inv1 = 1.f / lrow[mt][1];
#pragma unroll
        for (int nd = 0; nd < 8; nd++) {
            int col = h * DHEAD + nd * 8 + 2 * t;
            size_t row = rowbase + qbase + r0 + 16 * mt + g;
            *(float2*)&go[row * EMB + col] =
                make_float2(o[mt][nd][0] * inv0, o[mt][nd][1] * inv0);
            *(float2*)&go[(row + 8) * EMB + col] =
                make_float2(o[mt][nd][2] * inv1, o[mt][nd][3] * inv1);
        }
    }
}

// ---------------------------------------------------------------------------
extern "C" void kernel_launch(void* const* d_in, const int* in_sizes, int n_in,
                              void* d_out, int out_size) {
    const float* query = (const float*)d_in[0];
    const float* key   = (const float*)d_in[1];
    const float* value = (const float*)d_in[2];
    const float* Wq    = (const float*)d_in[3];
    const float* Wk    = (const float*)d_in[4];
    const float* Wv    = (const float*)d_in[5];
    const float* Wo    = (const float*)d_in[6];
    const float* Bq    = (const float*)d_in[7];
    const float* Bk    = (const float*)d_in[8];
    const float* Bv    = (const float*)d_in[9];
    const float* Bo    = (const float*)d_in[10];

    float *q, *k, *v, *attn;
    cudaGetSymbolAddress((void**)&q,    g_q);
    cudaGetSymbolAddress((void**)&k,    g_k);
    cudaGetSymbolAddress((void**)&v,    g_v);
    cudaGetSymbolAddress((void**)&attn, g_attn);

    cudaFuncSetAttribute(qkv_gemm, cudaFuncAttributeMaxDynamicSharedMemorySize, GEMM_SMEM);
    cudaFuncSetAttribute(out_gemm, cudaFuncAttributeMaxDynamicSharedMemorySize, GEMM_SMEM);
    cudaFuncSetAttribute(flash_mma, cudaFuncAttributeMaxDynamicSharedMemorySize, ATTN_SMEM);

    qkv_gemm<<<dim3(EMB / 128, MTOT / 128, 3), 256, GEMM_SMEM>>>(
        query, key, value, Wq, Wk, Wv, Bq, Bk, Bv, q, k, v);

    flash_mma<<<dim3(SLEN / BR, BATCH * HEADS), 128, ATTN_SMEM>>>(q, k, v, attn);

    out_gemm<<<dim3(EMB / 128, MTOT / 128), 256, GEMM_SMEM>>>(attn, Wo, Bo, (float*)d_out);
}

// round 7
// speedup vs baseline: 6.6062x; 1.9899x over previous
#include <cuda_runtime.h>
#include <cuda_fp16.h>
#include <cstdint>

#define EMB 1024
#define BATCH 2
#define SLEN 2048
#define HEADS 16
#define DHEAD 64
#define MTOT (BATCH * SLEN)   // 4096

// fp16 scratch (allocation-free rule: __device__ globals)
__device__ __half g_xh[3][MTOT * EMB];   // fp16 copies of query/key/value inputs
__device__ __half g_wth[4][EMB * EMB];   // W transposed: rows=n, k contiguous
__device__ __half g_qh[MTOT * EMB];
__device__ __half g_kh[MTOT * EMB];
__device__ __half g_vh[MTOT * EMB];
__device__ __half g_ah[MTOT * EMB];      // attention output (fp16)

// ---------------------------------------------------------------------------
// helpers: fp16 mma m16n8k16 (row.col, f32 accum)
//   A (16x16): a0=(g,2t),(g,2t+1) a1=(g+8,2t).. a2=(g,8+2t).. a3=(g+8,8+2t)..
//   B (16x8 col-major): b0={B[2t][g],B[2t+1][g]} b1={B[2t+8][g],B[2t+9][g]}
//   C: c0=(g,2t) c1=(g,2t+1) c2=(g+8,2t) c3=(g+8,2t+1)
// ---------------------------------------------------------------------------
__device__ __forceinline__ uint32_t smaddr(const void* p) {
    return (uint32_t)__cvta_generic_to_shared(p);
}
__device__ __forceinline__ void ldm4(uint32_t a[4], uint32_t addr) {
    asm volatile("ldmatrix.sync.aligned.m8n8.x4.shared.b16 {%0,%1,%2,%3}, [%4];"
                 : "=r"(a[0]), "=r"(a[1]), "=r"(a[2]), "=r"(a[3]) : "r"(addr));
}
__device__ __forceinline__ void ldm4t(uint32_t a[4], uint32_t addr) {
    asm volatile("ldmatrix.sync.aligned.m8n8.x4.trans.shared.b16 {%0,%1,%2,%3}, [%4];"
                 : "=r"(a[0]), "=r"(a[1]), "=r"(a[2]), "=r"(a[3]) : "r"(addr));
}
__device__ __forceinline__ void mma16(float c[4], const uint32_t a[4],
                                      uint32_t b0, uint32_t b1) {
    asm volatile(
        "mma.sync.aligned.m16n8k16.row.col.f32.f16.f16.f32 "
        "{%0,%1,%2,%3}, {%4,%5,%6,%7}, {%8,%9}, {%0,%1,%2,%3};"
        : "+f"(c[0]), "+f"(c[1]), "+f"(c[2]), "+f"(c[3])
        : "r"(a[0]), "r"(a[1]), "r"(a[2]), "r"(a[3]), "r"(b0), "r"(b1));
}
__device__ __forceinline__ void cpasync16(uint32_t saddr, const void* gaddr) {
    asm volatile("cp.async.cg.shared.global [%0], [%1], 16;" :: "r"(saddr), "l"(gaddr));
}
__device__ __forceinline__ uint32_t h2u(float lo, float hi) {
    __half2 h = __floats2half2_rn(lo, hi);
    return *(uint32_t*)&h;
}

// ---------------------------------------------------------------------------
// conversion pre-kernels
// ---------------------------------------------------------------------------
__global__ void conv_x3(const float* __restrict__ q, const float* __restrict__ k,
                        const float* __restrict__ v) {
    int z = blockIdx.z;
    const float* X = (z == 0) ? q : (z == 1) ? k : v;
    __half* out = g_xh[z];
    size_t gid = (size_t)blockIdx.x * 256 + threadIdx.x;
    float4 x = *(const float4*)&X[gid * 4];
    *(uint2*)&out[gid * 4] = make_uint2(h2u(x.x, x.y), h2u(x.z, x.w));
}

__global__ void conv_w(const float* __restrict__ Wq, const float* __restrict__ Wk,
                       const float* __restrict__ Wv, const float* __restrict__ Wo) {
    __shared__ float ws[64 * 65];
    int z = blockIdx.z;
    const float* W = (z == 0) ? Wq : (z == 1) ? Wk : (z == 2) ? Wv : Wo;
    __half* WT = g_wth[z];
    int n0 = blockIdx.x * 64, k0 = blockIdx.y * 64;
    int tid = threadIdx.x;
#pragma unroll
    for (int i = 0; i < 4; i++) {
        int s = tid + i * 256;
        int row = s >> 4, c4 = (s & 15) * 4;   // row = k within tile
        float4 w = *(const float4*)&W[(size_t)(k0 + row) * EMB + n0 + c4];
        ws[row * 65 + c4 + 0] = w.x; ws[row * 65 + c4 + 1] = w.y;
        ws[row * 65 + c4 + 2] = w.z; ws[row * 65 + c4 + 3] = w.w;
    }
    __syncthreads();
#pragma unroll
    for (int i = 0; i < 4; i++) {
        int s = tid + i * 256;
        int n = s >> 4, kq = s & 15;
        float a = ws[(kq * 4 + 0) * 65 + n], b = ws[(kq * 4 + 1) * 65 + n];
        float c = ws[(kq * 4 + 2) * 65 + n], d = ws[(kq * 4 + 3) * 65 + n];
        *(uint2*)&WT[(size_t)(n0 + n) * EMB + k0 + kq * 4] =
            make_uint2(h2u(a, b), h2u(c, d));
    }
}

// ---------------------------------------------------------------------------
// fp16 GEMM: Y[m0:+128, n0:+128] = X*W + bias. BK=32, 3-stage cp.async,
// 256 threads, 8 warps, warp tile 64x32, m16n8k16 mma.
// A smem [128][40] fp16 (stride 20 words, conflict-free); BT smem same.
// ---------------------------------------------------------------------------
#define GSTR 40
#define G_TILE_HALF (128 * GSTR)              // 5120 halves per operand tile
#define G_STAGE_BYTES (2 * G_TILE_HALF * 2)   // 20480
#define GEMM_SMEM (3 * G_STAGE_BYTES)         // 61440

__device__ __forceinline__
void gemm_core(const __half* __restrict__ Xh, const __half* __restrict__ Wt,
               const float* __restrict__ bias, void* Yout, int fp16_out, char* smem) {
    const int tid = threadIdx.x;
    const int lane = tid & 31;
    const int g = lane >> 2, t = lane & 3;
    const int wid = tid >> 5;
    const int wm = (wid >> 2) * 64;
    const int wn = (wid & 3) * 32;
    const int n0 = blockIdx.x * 128, m0 = blockIdx.y * 128;
    const uint32_t sb = smaddr(smem);

    auto issue = [&](int slot, int k0) {
        uint32_t ab = sb + (uint32_t)slot * G_STAGE_BYTES;
        uint32_t bb = ab + G_TILE_HALF * 2;
#pragma unroll
        for (int i = 0; i < 2; i++) {
            int f = tid + i * 256;
            int row = f >> 2, c8 = (f & 3) * 8;
            cpasync16(ab + (uint32_t)(row * GSTR + c8) * 2,
                      &Xh[(size_t)(m0 + row) * EMB + k0 + c8]);
            cpasync16(bb + (uint32_t)(row * GSTR + c8) * 2,
                      &Wt[(size_t)(n0 + row) * EMB + k0 + c8]);
        }
        asm volatile("cp.async.commit_group;");
    };
    issue(0, 0);
    issue(1, 32);

    float acc[4][4][4];
#pragma unroll
    for (int i = 0; i < 4; i++)
#pragma unroll
        for (int j = 0; j < 4; j++)
#pragma unroll
            for (int q = 0; q < 4; q++) acc[i][j][q] = 0.f;

    const int nit = EMB / 32;   // 32
    for (int it = 0; it < nit; it++) {
        asm volatile("cp.async.wait_group 1;");
        __syncthreads();
        if (it + 2 < nit) issue((it + 2) % 3, (it + 2) * 32);
        else asm volatile("cp.async.commit_group;");

        const __half* as = (const __half*)(smem + (it % 3) * G_STAGE_BYTES);
        const __half* bs = as + G_TILE_HALF;
#pragma unroll
        for (int ks = 0; ks < 2; ks++) {
            const int k0 = ks * 16;
            uint32_t a[4][4];
#pragma unroll
            for (int mi = 0; mi < 4; mi++)
                ldm4(a[mi], smaddr(&as[(wm + 16 * mi + (lane & 15)) * GSTR +
                                       k0 + (lane >> 4) * 8]));
            uint32_t b[4][2];
#pragma unroll
            for (int jp = 0; jp < 2; jp++) {
                uint32_t bbr[4];
                ldm4(bbr, smaddr(&bs[(wn + jp * 16 + ((lane >> 4) & 1) * 8 + (lane & 7)) * GSTR +
                                     k0 + ((lane >> 3) & 1) * 8]));
                b[2 * jp][0] = bbr[0]; b[2 * jp][1] = bbr[1];
                b[2 * jp + 1][0] = bbr[2]; b[2 * jp + 1][1] = bbr[3];
            }
#pragma unroll
            for (int mi = 0; mi < 4; mi++)
#pragma unroll
                for (int nj = 0; nj < 4; nj++)
                    mma16(acc[mi][nj], a[mi], b[nj][0], b[nj][1]);
        }
    }

#pragma unroll
    for (int mi = 0; mi < 4; mi++) {
#pragma unroll
        for (int nj = 0; nj < 4; nj++) {
            int col = n0 + wn + 8 * nj + 2 * t;
            float b0v = bias[col], b1v = bias[col + 1];
            int row = m0 + wm + 16 * mi + g;
            float o00 = acc[mi][nj][0] + b0v, o01 = acc[mi][nj][1] + b1v;
            float o10 = acc[mi][nj][2] + b0v, o11 = acc[mi][nj][3] + b1v;
            if (fp16_out) {
                __half* Y = (__half*)Yout;
                *(uint32_t*)&Y[(size_t)row * EMB + col] = h2u(o00, o01);
                *(uint32_t*)&Y[(size_t)(row + 8) * EMB + col] = h2u(o10, o11);
            } else {
                float* Y = (float*)Yout;
                *(float2*)&Y[(size_t)row * EMB + col] = make_float2(o00, o01);
                *(float2*)&Y[(size_t)(row + 8) * EMB + col] = make_float2(o10, o11);
            }
        }
    }
}

__global__ __launch_bounds__(256, 2)
void qkv_gemm(const float* __restrict__ Bq, const float* __restrict__ Bk,
              const float* __restrict__ Bv) {
    extern __shared__ char smem[];
    int z = blockIdx.z;
    const float* bias = (z == 0) ? Bq : (z == 1) ? Bk : Bv;
    __half* Y = (z == 0) ? g_qh : (z == 1) ? g_kh : g_vh;
    gemm_core(g_xh[z], g_wth[z], bias, Y, 1, smem);
}
__global__ __launch_bounds__(256, 2)
void out_gemm(const float* __restrict__ Bo, float* __restrict__ Y) {
    extern __shared__ char smem[];
    gemm_core(g_ah, g_wth[3], Bo, Y, 0, smem);
}

// ---------------------------------------------------------------------------
// fp16 flash attention: 4 warps x 32 rows (BR=128), Bc=64, D=64.
// Q in regs (ldmatrix once). K: plain ldmatrix B-frags. V: ldmatrix.trans.
// P: direct C-layout -> A-frag fp16 pack (no shuffles). 3-stage cp.async K/V.
// ---------------------------------------------------------------------------
#define FSTR 72
#define KV_STAGE_BYTES (2 * 64 * FSTR * 2)   // 18432
#define ATTN_SMEM (3 * KV_STAGE_BYTES)       // 55296

__global__ __launch_bounds__(128, 2)
void flash_fp16() {
    extern __shared__ char smem[];
    __half* sh = (__half*)smem;

    const int tid = threadIdx.x;
    const int lane = tid & 31;
    const int g = lane >> 2, t = lane & 3;
    const int wid = tid >> 5;
    const int r0 = wid * 32;
    const int qt = blockIdx.x, bh = blockIdx.y;
    const int b = bh >> 4, h = bh & 15;
    const int qbase = qt * 128;
    const size_t rowbase = (size_t)b * SLEN;

    // ---- stage Q (scaled by 1/8, exact in fp16), ldmatrix to regs
    const __half2 sc2 = __float2half2_rn(0.125f);
#pragma unroll
    for (int i = 0; i < 8; i++) {
        int f = tid + i * 128;
        int row = f >> 3, c8 = (f & 7) * 8;
        uint4 qv = *(const uint4*)&g_qh[(rowbase + qbase + row) * EMB + h * DHEAD + c8];
        __half2* hp = (__half2*)&qv;
        hp[0] = __hmul2(hp[0], sc2); hp[1] = __hmul2(hp[1], sc2);
        hp[2] = __hmul2(hp[2], sc2); hp[3] = __hmul2(hp[3], sc2);
        *(uint4*)&sh[row * FSTR + c8] = qv;
    }
    __syncthreads();

    uint32_t qf[2][4][4];
#pragma unroll
    for (int mt = 0; mt < 2; mt++)
#pragma unroll
        for (int kd = 0; kd < 4; kd++)
            ldm4(qf[mt][kd],
                 smaddr(&sh[(r0 + 16 * mt + (lane & 15)) * FSTR + kd * 16 + (lane >> 4) * 8]));
    __syncthreads();   // Q region reusable as stage 0

    const uint32_t shb = smaddr(sh);
    auto issue_kv = [&](int slot, int kt) {
        uint32_t kb = shb + (uint32_t)slot * KV_STAGE_BYTES;
        uint32_t vb = kb + 64 * FSTR * 2;
#pragma unroll
        for (int i = 0; i < 4; i++) {
            int f = tid + i * 128;
            int row = f >> 3, c8 = (f & 7) * 8;
            size_t gidx = (rowbase + kt + row) * EMB + h * DHEAD + c8;
            cpasync16(kb + (uint32_t)(row * FSTR + c8) * 2, &g_kh[gidx]);
            cpasync16(vb + (uint32_t)(row * FSTR + c8) * 2, &g_vh[gidx]);
        }
        asm volatile("cp.async.commit_group;");
    };
    issue_kv(0, 0);
    issue_kv(1, 64);

    float o[2][8][4];
#pragma unroll
    for (int mt = 0; mt < 2; mt++)
#pragma unroll
        for (int nd = 0; nd < 8; nd++)
#pragma unroll
            for (int q = 0; q < 4; q++) o[mt][nd][q] = 0.f;
    float mrow[2][2] = {{-1e30f, -1e30f}, {-1e30f, -1e30f}};
    float lrow[2][2] = {{0.f, 0.f}, {0.f, 0.f}};

    const int NIT = SLEN / 64;   // 32
    for (int it = 0; it < NIT; it++) {
        asm volatile("cp.async.wait_group 1;");
        __syncthreads();
        if (it + 2 < NIT) issue_kv((it + 2) % 3, (it + 2) * 64);
        else asm volatile("cp.async.commit_group;");

        const __half* Ks = (const __half*)(smem + (it % 3) * KV_STAGE_BYTES);
        const __half* Vs = Ks + 64 * FSTR;

        // ---- S = Q K^T (32 x 64 per warp)
        float s[2][8][4];
#pragma unroll
        for (int mt = 0; mt < 2; mt++)
#pragma unroll
            for (int nt = 0; nt < 8; nt++)
#pragma unroll
                for (int q = 0; q < 4; q++) s[mt][nt][q] = 0.f;

#pragma unroll
        for (int kd = 0; kd < 4; kd++) {
#pragma unroll
            for (int jp = 0; jp < 4; jp++) {
                uint32_t bb[4];
                ldm4(bb, smaddr(&Ks[(jp * 16 + ((lane >> 4) & 1) * 8 + (lane & 7)) * FSTR +
                                    kd * 16 + ((lane >> 3) & 1) * 8]));
#pragma unroll
                for (int mt = 0; mt < 2; mt++) {
                    mma16(s[mt][2 * jp],     qf[mt][kd], bb[0], bb[1]);
                    mma16(s[mt][2 * jp + 1], qf[mt][kd], bb[2], bb[3]);
                }
            }
        }

        // ---- online softmax (row groups: mt x {g, g+8})
#pragma unroll
        for (int mt = 0; mt < 2; mt++) {
            float rmax0 = -1e30f, rmax1 = -1e30f;
#pragma unroll
            for (int nt = 0; nt < 8; nt++) {
                rmax0 = fmaxf(rmax0, fmaxf(s[mt][nt][0], s[mt][nt][1]));
                rmax1 = fmaxf(rmax1, fmaxf(s[mt][nt][2], s[mt][nt][3]));
            }
            rmax0 = fmaxf(rmax0, __shfl_xor_sync(0xffffffffu, rmax0, 1));
            rmax0 = fmaxf(rmax0, __shfl_xor_sync(0xffffffffu, rmax0, 2));
            rmax1 = fmaxf(rmax1, __shfl_xor_sync(0xffffffffu, rmax1, 1));
            rmax1 = fmaxf(rmax1, __shfl_xor_sync(0xffffffffu, rmax1, 2));
            float mn0 = fmaxf(mrow[mt][0], rmax0);
            float mn1 = fmaxf(mrow[mt][1], rmax1);
            float cor0 = __expf(mrow[mt][0] - mn0);
            float cor1 = __expf(mrow[mt][1] - mn1);
            mrow[mt][0] = mn0; mrow[mt][1] = mn1;
            float sum0 = 0.f, sum1 = 0.f;
#pragma unroll
            for (int nt = 0; nt < 8; nt++) {
                s[mt][nt][0] = __expf(s[mt][nt][0] - mn0);
                s[mt][nt][1] = __expf(s[mt][nt][1] - mn0);
                s[mt][nt][2] = __expf(s[mt][nt][2] - mn1);
                s[mt][nt][3] = __expf(s[mt][nt][3] - mn1);
                sum0 += s[mt][nt][0] + s[mt][nt][1];
                sum1 += s[mt][nt][2] + s[mt][nt][3];
            }
            sum0 += __shfl_xor_sync(0xffffffffu, sum0, 1);
            sum0 += __shfl_xor_sync(0xffffffffu, sum0, 2);
            sum1 += __shfl_xor_sync(0xffffffffu, sum1, 1);
            sum1 += __shfl_xor_sync(0xffffffffu, sum1, 2);
            lrow[mt][0] = lrow[mt][0] * cor0 + sum0;
            lrow[mt][1] = lrow[mt][1] * cor1 + sum1;
#pragma unroll
            for (int nd = 0; nd < 8; nd++) {
                o[mt][nd][0] *= cor0; o[mt][nd][1] *= cor0;
                o[mt][nd][2] *= cor1; o[mt][nd][3] *= cor1;
            }
        }

        // ---- O += P V : P packs directly from C-layout to A-frag (no shfl)
#pragma unroll
        for (int kk = 0; kk < 4; kk++) {
            uint32_t ap[2][4];
#pragma unroll
            for (int mt = 0; mt < 2; mt++) {
                ap[mt][0] = h2u(s[mt][2 * kk][0],     s[mt][2 * kk][1]);
                ap[mt][1] = h2u(s[mt][2 * kk][2],     s[mt][2 * kk][3]);
                ap[mt][2] = h2u(s[mt][2 * kk + 1][0], s[mt][2 * kk + 1][1]);
                ap[mt][3] = h2u(s[mt][2 * kk + 1][2], s[mt][2 * kk + 1][3]);
            }
#pragma unroll
            for (int dp = 0; dp < 4; dp++) {
                uint32_t vb[4];
                ldm4t(vb, smaddr(&Vs[(kk * 16 + ((lane >> 3) & 1) * 8 + (lane & 7)) * FSTR +
                                     dp * 16 + ((lane >> 4) & 1) * 8]));
#pragma unroll
                for (int mt = 0; mt < 2; mt++) {
                    mma16(o[mt][2 * dp],     ap[mt], vb[0], vb[1]);
                    mma16(o[mt][2 * dp + 1], ap[mt], vb[2], vb[3]);
                }
            }
        }
    }

    // ---- normalize + write fp16 attn
#pragma unroll
    for (int mt = 0; mt < 2; mt++) {
        float inv0 = 1.f / lrow[mt][0], inv1 = 1.f / lrow[mt][1];
#pragma unroll
        for (int nd = 0; nd < 8; nd++) {
            int col = h * DHEAD + nd * 8 + 2 * t;
            size_t row = rowbase + qbase + r0 + 16 * mt + g;
            *(uint32_t*)&g_ah[row * EMB + col] =
                h2u(o[mt][nd][0] * inv0, o[mt][nd][1] * inv0);
            *(uint32_t*)&g_ah[(row + 8) * EMB + col] =
                h2u(o[mt][nd][2] * inv1, o[mt][nd][3] * inv1);
        }
    }
}

// ---------------------------------------------------------------------------
extern "C" void kernel_launch(void* const* d_in, const int* in_sizes, int n_in,
                              void* d_out, int out_size) {
    const float* query = (const float*)d_in[0];
    const float* key   = (const float*)d_in[1];
    const float* value = (const float*)d_in[2];
    const float* Wq    = (const float*)d_in[3];
    const float* Wk    = (const float*)d_in[4];
    const float* Wv    = (const float*)d_in[5];
    const float* Wo    = (const float*)d_in[6];
    const float* Bq    = (const float*)d_in[7];
    const float* Bk    = (const float*)d_in[8];
    const float* Bv    = (const float*)d_in[9];
    const float* Bo    = (const float*)d_in[10];

    cudaFuncSetAttribute(qkv_gemm, cudaFuncAttributeMaxDynamicSharedMemorySize, GEMM_SMEM);
    cudaFuncSetAttribute(out_gemm, cudaFuncAttributeMaxDynamicSharedMemorySize, GEMM_SMEM);
    cudaFuncSetAttribute(flash_fp16, cudaFuncAttributeMaxDynamicSharedMemorySize, ATTN_SMEM);

    conv_x3<<<dim3(MTOT * EMB / 1024, 1, 3), 256>>>(query, key, value);
    conv_w<<<dim3(16, 16, 4), 256>>>(Wq, Wk, Wv, Wo);

    qkv_gemm<<<dim3(EMB / 128, MTOT / 128, 3), 256, GEMM_SMEM>>>(Bq, Bk, Bv);

    flash_fp16<<<dim3(SLEN / 128, BATCH * HEADS), 128, ATTN_SMEM>>>();

    out_gemm<<<dim3(EMB / 128, MTOT / 128), 256, GEMM_SMEM>>>(Bo, (float*)d_out);
}